// round 13
// baseline (speedup 1.0000x reference)
#include <cuda_runtime.h>
#include <cstdint>

#define JAXPART 1
#define LOG2PI_F 1.8378770664093453f

__device__ double g_acc[4];                 // 0 qm0, 1 gpKL, 2 KL, 3 lik
__device__ float g_eps0[16*4*256*4];
__device__ float g_epsU[16*4*32];
__device__ float g_epsq[128*16*256*4];
__device__ float g_m0[256*4];
__device__ float g_v0[256*4];
__device__ float g_C[4*32*36];              // Lzz^-1, zero-padded rows of 36
__device__ float g_u[16*4*32];              // u' = C @ U
__device__ float g_par[256*128*36];

__host__ __device__ inline void tf2x32(uint32_t k0,uint32_t k1,uint32_t c0,uint32_t c1,
                                       uint32_t &o0,uint32_t &o1){
  uint32_t ks[3]={k0,k1,k0^k1^0x1BD11BDAu};
  uint32_t x0=c0+ks[0], x1=c1+ks[1];
  const int rA[4]={13,15,26,6}, rB[4]={17,29,16,24};
  for(int i=0;i<5;i++){
    const int* rr=(i&1)?rB:rA;
    for(int j=0;j<4;j++){ x0+=x1; int d=rr[j]; x1=(x1<<d)|(x1>>(32-d)); x1^=x0; }
    x0+=ks[(i+1)%3]; x1+=ks[(i+2)%3]+(uint32_t)(i+1);
  }
  o0=x0; o1=x1;
}

__device__ inline float erfinv_f(float x){
  float w=-log1pf(-x*x), p;
  if(w<5.0f){
    w-=2.5f;
    p=2.81022636e-08f;           p=fmaf(p,w,3.43273939e-07f);
    p=fmaf(p,w,-3.5233877e-06f); p=fmaf(p,w,-4.39150654e-06f);
    p=fmaf(p,w,0.00021858087f);  p=fmaf(p,w,-0.00125372503f);
    p=fmaf(p,w,-0.00417768164f); p=fmaf(p,w,0.246640727f);
    p=fmaf(p,w,1.50140941f);
  }else{
    w=sqrtf(w)-3.0f;
    p=-0.000200214257f;          p=fmaf(p,w,0.000100950558f);
    p=fmaf(p,w,0.00134934322f);  p=fmaf(p,w,-0.00367342844f);
    p=fmaf(p,w,0.00573950773f);  p=fmaf(p,w,-0.0076224613f);
    p=fmaf(p,w,0.00943887047f);  p=fmaf(p,w,1.00167406f);
    p=fmaf(p,w,2.83297682f);
  }
  return p*x;
}

__device__ inline float b2n(uint32_t bits){
  float f=__uint_as_float((bits>>9)|0x3f800000u)-1.0f;
  const float lo=-0.99999994f;
  float u=fmaxf(lo, f*2.0f+lo);
  return 1.41421356237f*erfinv_f(u);
}

__global__ void k_zero(){ if(threadIdx.x<4) g_acc[threadIdx.x]=0.0; }

__global__ void k_prng(uint32_t ka,uint32_t kb,int sel,int n){
  int j=blockIdx.x*blockDim.x+threadIdx.x;
  float* out=(sel==0)?g_eps0:(sel==1)?g_epsU:g_epsq;
#if JAXPART
  if(j>=n) return;
  uint32_t a,b; tf2x32(ka,kb,0u,(uint32_t)j,a,b);
  out[j]=b2n(a^b);
#else
  int h=n>>1; if(j>=h) return;
  uint32_t a,b; tf2x32(ka,kb,(uint32_t)j,(uint32_t)(j+h),a,b);
  out[j]=b2n(a); out[j+h]=b2n(b);
#endif
}

// ---- Kzz, Cholesky, C = L^-1, gpKL ----
__global__ void k_prep(const float* Z,const float* lls,const float* los,
                       const float* m_u,const float* Lu){
  __shared__ float A[4][1056], Cs[4][1056];
  int d=threadIdx.x>>5, l=threadIdx.x&31;
  unsigned FM=0xffffffffu;
  float il[4], zl[4];
  for(int k=0;k<4;k++){ il[k]=expf(-lls[d*4+k]); zl[k]=Z[(d*32+l)*4+k]; }
  float osd=expf(los[d]);
  for(int i=0;i<32;i++){
    float s=0;
    for(int k=0;k<4;k++){ float df=(Z[(d*32+i)*4+k]-zl[k])*il[k]; s+=df*df; }
    A[d][i*33+l]=osd*expf(-0.5f*s)+((i==l)?1e-5f:0.f);
  }
  __syncwarp();
  for(int j=0;j<32;j++){
    float s=0.f;
    if(l>=j){ s=A[d][l*33+j]; for(int k=0;k<j;k++) s-=A[d][l*33+k]*A[d][j*33+k]; }
    float dj=sqrtf(__shfl_sync(FM,s,j));
    if(l==j) A[d][l*33+j]=dj; else if(l>j) A[d][l*33+j]=s/dj;
    __syncwarp();
  }
  for(int i=0;i<32;i++){
    float s=(i==l)?1.f:0.f;
    for(int k=l;k<i;k++) s-=A[d][i*33+k]*Cs[d][k*33+l];
    Cs[d][i*33+l]=(i>=l)?s/A[d][i*33+i]:0.f;
    __syncwarp();
  }
  for(int idx=l; idx<32*36; idx+=32){
    int m=idx/36, j=idx%36;
    g_C[d*1152+idx]=(j<32&&j<=m)?Cs[d][m*33+j]:0.f;
  }
  // gpKL pieces
  float accA=0.f;
  for(int i=0;i<32;i++){
    float a=0.f;
    for(int j=l;j<=i;j++) a+=Cs[d][i*33+j]*Lu[(d*32+j)*32+l];
    accA+=a*a;
  }
  float bq;
  { float s=0.f; for(int j=0;j<=l;j++) s+=Cs[d][l*33+j]*m_u[d*32+j]; bq=s*s; }
  float ldK=2.f*logf(A[d][l*33+l]);
  float ldS=2.f*logf(fabsf(Lu[(d*32+l)*32+l])+1e-12f);
  float tot=accA+bq-1.f+ldK-ldS;
  for(int o=16;o;o>>=1) tot+=__shfl_xor_sync(FM,tot,o);
  if(l==0) atomicAdd(&g_acc[1],0.5*(double)tot/(128.0*256.0));
}

// ---- U = m_u + tril(Lu) epsU ; u' = C U ----
__global__ void k_uprep(const float* m_u,const float* Lu){
  int gt=blockIdx.x*blockDim.x+threadIdx.x;
  int w=gt>>5, l=gt&31;
  if(w>=64) return;
  int n=w>>2, d=w&3;
  unsigned FM=0xffffffffu;
  float e=g_epsU[(n*4+d)*32+l];
  float U=m_u[d*32+l];
  for(int k=0;k<32;k++){
    float ek=__shfl_sync(FM,e,k);
    float lv=(k<=l)?Lu[(d*32+l)*32+k]:0.f;
    U=fmaf(lv,ek,U);
  }
  float s=0.f;
  for(int j=0;j<32;j++){
    float Uj=__shfl_sync(FM,U,j);
    s=fmaf(g_C[d*1152+l*36+j],Uj,s);
  }
  g_u[(n*4+d)*32+l]=s;
}

__device__ inline float sigf(float x){ return 1.f/(1.f+expf(-x)); }

// ---- LSTM encoder + m0/v0/qm0 ----
__global__ void __launch_bounds__(64) k_lstm(const float* obs,const float* Wih,
    const float* Whh,const float* bl,const float* Wm,const float* bm,
    const float* Wv,const float* bv){
  extern __shared__ float sm[];
  float* whh=sm;               // 256*65
  float* wih=whh+256*65;       // 256*4
  float* bb =wih+256*4;        // 256
  float* hs =bb+256;           // 64
  int b=blockIdx.x, tid=threadIdx.x;
  for(int idx=tid; idx<256*64; idx+=64) whh[(idx>>6)*65+(idx&63)]=Whh[idx];
  for(int idx=tid; idx<256; idx+=64){
    wih[idx*4]=Wih[idx*3]; wih[idx*4+1]=Wih[idx*3+1]; wih[idx*4+2]=Wih[idx*3+2];
    bb[idx]=bl[idx];
  }
  hs[tid]=0.f;
  __syncthreads();
  int h=tid;
  float c=0.f;
  int ri=h, rf=64+h, rg=128+h, ro=192+h;
  for(int t=0;t<128;t++){
    float x0=obs[(b*128+t)*3], x1=obs[(b*128+t)*3+1], x2=obs[(b*128+t)*3+2];
    float gi=bb[ri]+wih[ri*4]*x0+wih[ri*4+1]*x1+wih[ri*4+2]*x2;
    float gf=bb[rf]+wih[rf*4]*x0+wih[rf*4+1]*x1+wih[rf*4+2]*x2;
    float gg=bb[rg]+wih[rg*4]*x0+wih[rg*4+1]*x1+wih[rg*4+2]*x2;
    float go=bb[ro]+wih[ro*4]*x0+wih[ro*4+1]*x1+wih[ro*4+2]*x2;
    for(int k=0;k<64;k++){
      float hk=hs[k];
      gi=fmaf(whh[ri*65+k],hk,gi); gf=fmaf(whh[rf*65+k],hk,gf);
      gg=fmaf(whh[rg*65+k],hk,gg); go=fmaf(whh[ro*65+k],hk,go);
    }
    c=sigf(gf)*c+sigf(gi)*tanhf(gg);
    float hn=sigf(go)*tanhf(c);
    __syncthreads();
    hs[h]=hn;
    __syncthreads();
  }
  if(tid<4){
    int s=tid;
    float m=bm[s], pv=bv[s];
    for(int k=0;k<64;k++){ m=fmaf(Wm[s*64+k],hs[k],m); pv=fmaf(Wv[s*64+k],hs[k],pv); }
    float v=fmaxf(pv,0.f)+log1pf(expf(-fabsf(pv)))+1e-6f;
    g_m0[b*4+s]=m; g_v0[b*4+s]=v;
    atomicAdd(&g_acc[0],0.5*(double)(v+m*m-1.f-logf(v)));
  }
}

// ---- fused 4-layer MLP -> par ----
__global__ void __launch_bounds__(256) k_mlp(const float* obs,
  const float* W1,const float* b1,const float* W2,const float* b2,
  const float* W3,const float* b3,const float* W4,const float* b4){
  extern __shared__ __align__(16) float sm[];
  float* W2s=sm;                    // 128*260
  float* W3s=W2s+128*260;           // 64*132
  float* W4s=W3s+64*132;            // 36*68
  float* W1s=W4s+36*68;             // 256*4
  float* b1s=W1s+1024; float* b2s=b1s+256; float* b3s=b2s+128; float* b4s=b3s+64;
  float* h1t=b4s+64;                // 16*260 (reused as h3t, stride 68)
  float* h2t=h1t+16*260;            // 16*132
  int tid=threadIdx.x;
  for(int i=tid;i<128*256;i+=256) W2s[(i>>8)*260+(i&255)]=W2[i];
  for(int i=tid;i<64*128;i+=256)  W3s[(i>>7)*132+(i&127)]=W3[i];
  for(int i=tid;i<36*64;i+=256)   W4s[(i>>6)*68+(i&63)]=W4[i];
  if(tid<256){ W1s[tid*4]=W1[tid*3]; W1s[tid*4+1]=W1[tid*3+1]; W1s[tid*4+2]=W1[tid*3+2]; b1s[tid]=b1[tid]; }
  if(tid<128) b2s[tid]=b2[tid];
  if(tid<64)  b3s[tid]=b3[tid];
  if(tid<36)  b4s[tid]=b4[tid];
  __syncthreads();
  int rb=blockIdx.x*128;
  for(int tile=0;tile<8;tile++){
    int r0=rb+tile*16;
    for(int i=tid;i<16*256;i+=256){
      int r=i>>8, j=i&255, row=r0+r;
      float a=b1s[j]+W1s[j*4]*obs[row*3]+W1s[j*4+1]*obs[row*3+1]+W1s[j*4+2]*obs[row*3+2];
      h1t[r*260+j]=fmaxf(a,0.f);
    }
    __syncthreads();
    for(int i=tid;i<16*128;i+=256){
      int r=i>>7, j=i&127;
      float a=b2s[j];
      const float4* w=(const float4*)(W2s+j*260);
      const float4* hv=(const float4*)(h1t+r*260);
      #pragma unroll 8
      for(int k=0;k<64;k++){ float4 wv=w[k],h4=hv[k];
        a=fmaf(wv.x,h4.x,a); a=fmaf(wv.y,h4.y,a); a=fmaf(wv.z,h4.z,a); a=fmaf(wv.w,h4.w,a); }
      h2t[r*132+j]=fmaxf(a,0.f);
    }
    __syncthreads();
    for(int i=tid;i<16*64;i+=256){
      int r=i>>6, j=i&63;
      float a=b3s[j];
      const float4* w=(const float4*)(W3s+j*132);
      const float4* hv=(const float4*)(h2t+r*132);
      #pragma unroll 8
      for(int k=0;k<32;k++){ float4 wv=w[k],h4=hv[k];
        a=fmaf(wv.x,h4.x,a); a=fmaf(wv.y,h4.y,a); a=fmaf(wv.z,h4.z,a); a=fmaf(wv.w,h4.w,a); }
      h1t[r*68+j]=fmaxf(a,0.f);
    }
    __syncthreads();
    for(int i=tid;i<16*36;i+=256){
      int r=i/36, j=i%36;
      float a=b4s[j];
      const float4* w=(const float4*)(W4s+j*68);
      const float4* hv=(const float4*)(h1t+r*68);
      #pragma unroll
      for(int k=0;k<16;k++){ float4 wv=w[k],h4=hv[k];
        a=fmaf(wv.x,h4.x,a); a=fmaf(wv.y,h4.y,a); a=fmaf(wv.z,h4.z,a); a=fmaf(wv.w,h4.w,a); }
      g_par[(r0+r)*36+j]=a;
    }
    __syncthreads();
  }
}

// ---- main scan: warp per (n,b) chain, 128 steps ----
__global__ void __launch_bounds__(256) k_step(const float* Z,const float* lls,
    const float* los,const float* npc,const float* nem,const float* obs){
  __shared__ __align__(16) float Cs[4608];
  __shared__ __align__(16) float kb[8][36];
  int tid=threadIdx.x, wid=tid>>5, l=tid&31;
  unsigned FM=0xffffffffu;
  for(int i=tid;i<4608;i+=256) Cs[i]=g_C[i];
  int c=blockIdx.x*8+wid;
  int n=c>>8, b=c&255;
  float zl[4][4], il[4][4], osd[4], ul[4], np_[4], ne[3], lne[3];
  #pragma unroll
  for(int d=0;d<4;d++){
    osd[d]=expf(los[d]); np_[d]=npc[d];
    ul[d]=g_u[(n*4+d)*32+l];
    #pragma unroll
    for(int k=0;k<4;k++){ il[d][k]=expf(-lls[d*4+k]); zl[d][k]=Z[(d*32+l)*4+k]; }
  }
  #pragma unroll
  for(int o=0;o<3;o++){ ne[o]=nem[o]; lne[o]=logf(ne[o]); }
  float x[4][4];
  #pragma unroll
  for(int d=0;d<4;d++)
    #pragma unroll
    for(int k=0;k<4;k++)
      x[d][k]=g_m0[b*4+k]+sqrtf(g_v0[b*4+k])*g_eps0[((n*4+d)*256+b)*4+k];
  __syncthreads();
  double klacc=0.0, likacc=0.0;
  for(int t=0;t<128;t++){
    float pm[4], pv[4];
    #pragma unroll
    for(int d=0;d<4;d++){
      float s=0.f;
      #pragma unroll
      for(int k=0;k<4;k++){ float df=(x[d][k]-zl[d][k])*il[d][k]; s=fmaf(df,df,s); }
      float kx=osd[d]*expf(-0.5f*s);
      __syncwarp();
      kb[wid][l]=kx;
      __syncwarp();
      float4 kq[8];
      const float4* kbq=(const float4*)&kb[wid][0];
      #pragma unroll
      for(int j=0;j<8;j++) kq[j]=kbq[j];
      float w=0.f;
      const float4* Crow=(const float4*)(Cs+d*1152+l*36);
      #pragma unroll
      for(int j=0;j<8;j++){
        if(j*4<=l){
          float4 cv=Crow[j];
          w=fmaf(cv.x,kq[j].x,w); w=fmaf(cv.y,kq[j].y,w);
          w=fmaf(cv.z,kq[j].z,w); w=fmaf(cv.w,kq[j].w,w);
        }
      }
      pm[d]=w*ul[d]; pv[d]=w*w;
    }
    #pragma unroll
    for(int o=16;o;o>>=1){
      #pragma unroll
      for(int d=0;d<4;d++){
        pm[d]+=__shfl_xor_sync(FM,pm[d],o);
        pv[d]+=__shfl_xor_sync(FM,pv[d],o);
      }
    }
    float gm[4], gv[4];
    #pragma unroll
    for(int d=0;d<4;d++){ gm[d]=pm[d]; gv[d]=fmaxf(osd[d]-pv[d],1e-8f); }
    const float* pr=g_par+(b*128+t)*36;
    float Atm[16], btv[4], Sl[16];
    #pragma unroll
    for(int i=0;i<16;i++) Atm[i]=pr[i];
    #pragma unroll
    for(int i=0;i<4;i++) btv[i]=pr[16+i];
    #pragma unroll
    for(int i=0;i<16;i++) Sl[i]=((i&3)<=(i>>2))?pr[20+i]:0.f;
    float qm[4];
    #pragma unroll
    for(int i=0;i<4;i++){
      float s=btv[i];
      #pragma unroll
      for(int j=0;j<4;j++) s=fmaf(Atm[i*4+j],gm[j],s);
      qm[i]=s;
    }
    float qc[16];
    #pragma unroll
    for(int i=0;i<4;i++)
      #pragma unroll
      for(int k2=0;k2<4;k2++){
        if(k2>i) continue;
        float s=0.f;
        #pragma unroll
        for(int j=0;j<4;j++) s=fmaf(Sl[i*4+j],Sl[k2*4+j],s);
        #pragma unroll
        for(int j=0;j<4;j++) s=fmaf(Atm[i*4+j]*gv[j],Atm[k2*4+j],s);
        qc[i*4+k2]=s; qc[k2*4+i]=s;
      }
    float l00=sqrtf(qc[0]+1e-6f), i0=1.f/l00;
    float l10=qc[4]*i0, l20=qc[8]*i0, l30=qc[12]*i0;
    float l11=sqrtf(qc[5]+1e-6f-l10*l10), i1=1.f/l11;
    float l21=(qc[9]-l20*l10)*i1, l31=(qc[13]-l30*l10)*i1;
    float l22=sqrtf(qc[10]+1e-6f-l20*l20-l21*l21), i2=1.f/l22;
    float l32=(qc[14]-l30*l20-l31*l21)*i2;
    float l33=sqrtf(qc[15]+1e-6f-l30*l30-l31*l31-l32*l32);
    float logdet=2.f*(logf(l00)+logf(l11)+logf(l22)+logf(l33));
    float kl=0.f;
    #pragma unroll
    for(int i=0;i<4;i++){
      float d0=gv[i]+np_[i];
      float df=gm[i]-qm[i];
      kl+=(qc[i*4+i]+df*df)/d0+logf(d0);
    }
    kl=0.5f*(kl-4.f-logdet);
    float el=0.f;
    #pragma unroll
    for(int o=0;o<3;o++){
      float y=obs[(b*128+t)*3+o];
      float r=y-qm[o];
      el-=0.5f*(LOG2PI_F+lne[o]+(r*r+qc[o*4+o])/ne[o]);
    }
    klacc+=(double)kl; likacc+=(double)el;
    const float* ep=g_epsq+((t*16+n)*256+b)*4;
    float e0=ep[0],e1=ep[1],e2=ep[2],e3=ep[3];
    float xn0=qm[0]+l00*e0;
    float xn1=qm[1]+l10*e0+l11*e1;
    float xn2=qm[2]+l20*e0+l21*e1+l22*e2;
    float xn3=qm[3]+l30*e0+l31*e1+l32*e2+l33*e3;
    #pragma unroll
    for(int d=0;d<4;d++){ x[d][0]=xn0; x[d][1]=xn1; x[d][2]=xn2; x[d][3]=xn3; }
  }
  if(l==0){
    atomicAdd(&g_acc[2],klacc);
    atomicAdd(&g_acc[3],likacc);
  }
}

__global__ void k_fin(float* out){
  double qm0=g_acc[0]/256.0, gpKL=g_acc[1];
  double KL=g_acc[2]/4096.0, lik=g_acc[3]/4096.0;
  double E=-qm0-gpKL+lik-KL;
  if(lik>KL) E=-qm0-gpKL+lik/128.0-KL;
  out[0]=(float)E;
}

extern "C" void kernel_launch(void* const* d_in, const int* in_sizes, int n_in,
                              void* d_out, int out_size){
  const float* obs=(const float*)d_in[0];
  const float* Z  =(const float*)d_in[1];
  const float* lls=(const float*)d_in[2];
  const float* los=(const float*)d_in[3];
  const float* m_u=(const float*)d_in[4];
  const float* Lu =(const float*)d_in[5];
  const float* npc=(const float*)d_in[6];
  const float* nem=(const float*)d_in[7];
  const float* Wih=(const float*)d_in[8];
  const float* Whh=(const float*)d_in[9];
  const float* bl =(const float*)d_in[10];
  const float* Wm =(const float*)d_in[11];
  const float* bm =(const float*)d_in[12];
  const float* Wv =(const float*)d_in[13];
  const float* bv =(const float*)d_in[14];
  const float* W1 =(const float*)d_in[15];
  const float* b1 =(const float*)d_in[16];
  const float* W2 =(const float*)d_in[17];
  const float* b2 =(const float*)d_in[18];
  const float* W3 =(const float*)d_in[19];
  const float* b3 =(const float*)d_in[20];
  const float* W4 =(const float*)d_in[21];
  const float* b4 =(const float*)d_in[22];

  // split key(42) -> k0 (eps0), kU (epsU), kq (eps_q)
  uint32_t K0a,K0b,KUa,KUb,KQa,KQb;
#if JAXPART
  // _threefry_split_foldlike: subkey_i = full pair of threefry(key, hi=0, lo=i)
  tf2x32(0u,42u,0u,0u,K0a,K0b);
  tf2x32(0u,42u,0u,1u,KUa,KUb);
  tf2x32(0u,42u,0u,2u,KQa,KQb);
#else
  uint32_t a0,b0,a1,b1_,a2,b2_;
  tf2x32(0u,42u,0u,3u,a0,b0); tf2x32(0u,42u,1u,4u,a1,b1_); tf2x32(0u,42u,2u,5u,a2,b2_);
  K0a=a0; K0b=a1; KUa=a2; KUb=b0; KQa=b1_; KQb=b2_;
#endif

  cudaFuncSetAttribute(k_lstm, cudaFuncAttributeMaxDynamicSharedMemorySize, 72192);
  cudaFuncSetAttribute(k_mlp,  cudaFuncAttributeMaxDynamicSharedMemorySize, 207936);

  k_zero<<<1,32>>>();
#if JAXPART
  k_prng<<<(65536+255)/256,256>>>(K0a,K0b,0,65536);
  k_prng<<<(2048+255)/256,256>>>(KUa,KUb,1,2048);
  k_prng<<<(2097152+255)/256,256>>>(KQa,KQb,2,2097152);
#else
  k_prng<<<(32768+255)/256,256>>>(K0a,K0b,0,65536);
  k_prng<<<(1024+255)/256,256>>>(KUa,KUb,1,2048);
  k_prng<<<(1048576+255)/256,256>>>(KQa,KQb,2,2097152);
#endif
  k_prep<<<1,128>>>(Z,lls,los,m_u,Lu);
  k_uprep<<<2,1024>>>(m_u,Lu);
  k_lstm<<<256,64,72192>>>(obs,Wih,Whh,bl,Wm,bm,Wv,bv);
  k_mlp<<<256,256,207936>>>(obs,W1,b1,W2,b2,W3,b3,W4,b4);
  k_step<<<512,256>>>(Z,lls,los,npc,nem,obs);
  k_fin<<<1,1>>>((float*)d_out);
}

// round 14
// speedup vs baseline: 1.2978x; 1.2978x over previous
#include <cuda_runtime.h>
#include <cstdint>

#define LOG2PI_F 1.8378770664093453f

__device__ double g_acc[4];                 // 0 qm0, 1 gpKL, 2 KL, 3 lik
__device__ float g_eps0[16*4*256*4];
__device__ float g_epsU[16*4*32];
__device__ float g_epsq[128*16*256*4];
__device__ float g_m0[256*4];
__device__ float g_v0[256*4];
__device__ float g_C[4*32*36];              // Lzz^-1, zero-padded rows of 36
__device__ float g_u[16*4*32];              // u' = C @ U
__device__ float g_par[256*128*36];

__host__ __device__ inline void tf2x32(uint32_t k0,uint32_t k1,uint32_t c0,uint32_t c1,
                                       uint32_t &o0,uint32_t &o1){
  uint32_t ks[3]={k0,k1,k0^k1^0x1BD11BDAu};
  uint32_t x0=c0+ks[0], x1=c1+ks[1];
  const int rA[4]={13,15,26,6}, rB[4]={17,29,16,24};
  for(int i=0;i<5;i++){
    const int* rr=(i&1)?rB:rA;
    for(int j=0;j<4;j++){ x0+=x1; int d=rr[j]; x1=(x1<<d)|(x1>>(32-d)); x1^=x0; }
    x0+=ks[(i+1)%3]; x1+=ks[(i+2)%3]+(uint32_t)(i+1);
  }
  o0=x0; o1=x1;
}

__device__ inline float erfinv_f(float x){
  float w=-log1pf(-x*x), p;
  if(w<5.0f){
    w-=2.5f;
    p=2.81022636e-08f;           p=fmaf(p,w,3.43273939e-07f);
    p=fmaf(p,w,-3.5233877e-06f); p=fmaf(p,w,-4.39150654e-06f);
    p=fmaf(p,w,0.00021858087f);  p=fmaf(p,w,-0.00125372503f);
    p=fmaf(p,w,-0.00417768164f); p=fmaf(p,w,0.246640727f);
    p=fmaf(p,w,1.50140941f);
  }else{
    w=sqrtf(w)-3.0f;
    p=-0.000200214257f;          p=fmaf(p,w,0.000100950558f);
    p=fmaf(p,w,0.00134934322f);  p=fmaf(p,w,-0.00367342844f);
    p=fmaf(p,w,0.00573950773f);  p=fmaf(p,w,-0.0076224613f);
    p=fmaf(p,w,0.00943887047f);  p=fmaf(p,w,1.00167406f);
    p=fmaf(p,w,2.83297682f);
  }
  return p*x;
}

__device__ inline float b2n(uint32_t bits){
  float f=__uint_as_float((bits>>9)|0x3f800000u)-1.0f;
  const float lo=-0.99999994f;
  float u=fmaxf(lo, f*2.0f+lo);
  return 1.41421356237f*erfinv_f(u);
}

// ---- all PRNG streams + accumulator zeroing in ONE launch ----
// segments: [0,65536) eps0 | [65536,67584) epsU | [67584,2164736) epsq
__global__ void k_prng_all(uint32_t K0a,uint32_t K0b,uint32_t KUa,uint32_t KUb,
                           uint32_t KQa,uint32_t KQb){
  int j=blockIdx.x*blockDim.x+threadIdx.x;
  if(j<4) g_acc[j]=0.0;
  if(j>=2164736) return;
  uint32_t ka,kb; float* out; int lj;
  if(j<65536){ ka=K0a; kb=K0b; out=g_eps0; lj=j; }
  else if(j<67584){ ka=KUa; kb=KUb; out=g_epsU; lj=j-65536; }
  else { ka=KQa; kb=KQb; out=g_epsq; lj=j-67584; }
  uint32_t a,b; tf2x32(ka,kb,0u,(uint32_t)lj,a,b);
  out[lj]=b2n(a^b);
}

// ---- Kzz, Cholesky, C = L^-1, gpKL ----
__global__ void k_prep(const float* Z,const float* lls,const float* los,
                       const float* m_u,const float* Lu){
  __shared__ float A[4][1056], Cs[4][1056];
  int d=threadIdx.x>>5, l=threadIdx.x&31;
  unsigned FM=0xffffffffu;
  float il[4], zl[4];
  for(int k=0;k<4;k++){ il[k]=expf(-lls[d*4+k]); zl[k]=Z[(d*32+l)*4+k]; }
  float osd=expf(los[d]);
  for(int i=0;i<32;i++){
    float s=0;
    for(int k=0;k<4;k++){ float df=(Z[(d*32+i)*4+k]-zl[k])*il[k]; s+=df*df; }
    A[d][i*33+l]=osd*expf(-0.5f*s)+((i==l)?1e-5f:0.f);
  }
  __syncwarp();
  for(int j=0;j<32;j++){
    float s=0.f;
    if(l>=j){ s=A[d][l*33+j]; for(int k=0;k<j;k++) s-=A[d][l*33+k]*A[d][j*33+k]; }
    float dj=sqrtf(__shfl_sync(FM,s,j));
    if(l==j) A[d][l*33+j]=dj; else if(l>j) A[d][l*33+j]=s/dj;
    __syncwarp();
  }
  for(int i=0;i<32;i++){
    float s=(i==l)?1.f:0.f;
    for(int k=l;k<i;k++) s-=A[d][i*33+k]*Cs[d][k*33+l];
    Cs[d][i*33+l]=(i>=l)?s/A[d][i*33+i]:0.f;
    __syncwarp();
  }
  for(int idx=l; idx<32*36; idx+=32){
    int m=idx/36, j=idx%36;
    g_C[d*1152+idx]=(j<32&&j<=m)?Cs[d][m*33+j]:0.f;
  }
  float accA=0.f;
  for(int i=0;i<32;i++){
    float a=0.f;
    for(int j=l;j<=i;j++) a+=Cs[d][i*33+j]*Lu[(d*32+j)*32+l];
    accA+=a*a;
  }
  float bq;
  { float s=0.f; for(int j=0;j<=l;j++) s+=Cs[d][l*33+j]*m_u[d*32+j]; bq=s*s; }
  float ldK=2.f*logf(A[d][l*33+l]);
  float ldS=2.f*logf(fabsf(Lu[(d*32+l)*32+l])+1e-12f);
  float tot=accA+bq-1.f+ldK-ldS;
  for(int o=16;o;o>>=1) tot+=__shfl_xor_sync(FM,tot,o);
  if(l==0) atomicAdd(&g_acc[1],0.5*(double)tot/(128.0*256.0));
}

// ---- U = m_u + tril(Lu) epsU ; u' = C U ----
__global__ void k_uprep(const float* m_u,const float* Lu){
  int gt=blockIdx.x*blockDim.x+threadIdx.x;
  int w=gt>>5, l=gt&31;
  if(w>=64) return;
  int n=w>>2, d=w&3;
  unsigned FM=0xffffffffu;
  float e=g_epsU[(n*4+d)*32+l];
  float U=m_u[d*32+l];
  for(int k=0;k<32;k++){
    float ek=__shfl_sync(FM,e,k);
    float lv=(k<=l)?Lu[(d*32+l)*32+k]:0.f;
    U=fmaf(lv,ek,U);
  }
  float s=0.f;
  for(int j=0;j<32;j++){
    float Uj=__shfl_sync(FM,U,j);
    s=fmaf(g_C[d*1152+l*36+j],Uj,s);
  }
  g_u[(n*4+d)*32+l]=s;
}

__device__ inline float sigf(float x){ return 1.f/(1.f+expf(-x)); }

// ---- LSTM encoder: 2 batches per block, float4 inner loop ----
__global__ void __launch_bounds__(128) k_lstm(const float* obs,const float* Wih,
    const float* Whh,const float* bl,const float* Wm,const float* bm,
    const float* Wv,const float* bv){
  extern __shared__ __align__(16) float sm[];
  float* whh=sm;               // 256*68 (stride 68, float4-aligned, conflict-free)
  float* wih=whh+256*68;       // 256*4
  float* bb =wih+1024;         // 256
  float* ob =bb+256;           // 2*128*4
  float* hs =ob+1024;          // 2*68
  int tid=threadIdx.x, g=tid>>6, h=tid&63;
  for(int idx=tid; idx<256*64; idx+=128){ int r=idx>>6,c2=idx&63; whh[r*68+c2]=Whh[idx]; }
  for(int idx=tid; idx<256; idx+=128){
    wih[idx*4]=Wih[idx*3]; wih[idx*4+1]=Wih[idx*3+1]; wih[idx*4+2]=Wih[idx*3+2];
    bb[idx]=bl[idx];
  }
  for(int idx=tid; idx<2*128*3; idx+=128){
    int gg=idx/384, rem=idx%384, t=rem/3, c2=rem%3;
    ob[(gg*128+t)*4+c2]=obs[((blockIdx.x*2+gg)*128+t)*3+c2];
  }
  hs[g*68+h]=0.f;
  __syncthreads();
  float c=0.f;
  int ri=h, rf=64+h, rg=128+h, ro=192+h;
  const float* myob=ob+g*512;
  float* myh=hs+g*68;
  int b=blockIdx.x*2+g;
  for(int t=0;t<128;t++){
    float x0=myob[t*4], x1=myob[t*4+1], x2=myob[t*4+2];
    float gi=bb[ri]+wih[ri*4]*x0+wih[ri*4+1]*x1+wih[ri*4+2]*x2;
    float gf=bb[rf]+wih[rf*4]*x0+wih[rf*4+1]*x1+wih[rf*4+2]*x2;
    float gg=bb[rg]+wih[rg*4]*x0+wih[rg*4+1]*x1+wih[rg*4+2]*x2;
    float go=bb[ro]+wih[ro*4]*x0+wih[ro*4+1]*x1+wih[ro*4+2]*x2;
    #pragma unroll 4
    for(int k=0;k<64;k+=4){
      float4 h4=*(const float4*)(myh+k);
      float4 wA=*(const float4*)(whh+ri*68+k);
      float4 wB=*(const float4*)(whh+rf*68+k);
      float4 wC=*(const float4*)(whh+rg*68+k);
      float4 wD=*(const float4*)(whh+ro*68+k);
      gi=fmaf(wA.x,h4.x,gi); gi=fmaf(wA.y,h4.y,gi); gi=fmaf(wA.z,h4.z,gi); gi=fmaf(wA.w,h4.w,gi);
      gf=fmaf(wB.x,h4.x,gf); gf=fmaf(wB.y,h4.y,gf); gf=fmaf(wB.z,h4.z,gf); gf=fmaf(wB.w,h4.w,gf);
      gg=fmaf(wC.x,h4.x,gg); gg=fmaf(wC.y,h4.y,gg); gg=fmaf(wC.z,h4.z,gg); gg=fmaf(wC.w,h4.w,gg);
      go=fmaf(wD.x,h4.x,go); go=fmaf(wD.y,h4.y,go); go=fmaf(wD.z,h4.z,go); go=fmaf(wD.w,h4.w,go);
    }
    c=sigf(gf)*c+sigf(gi)*tanhf(gg);
    float hn=sigf(go)*tanhf(c);
    __syncthreads();
    myh[h]=hn;
    __syncthreads();
  }
  if(h<4){
    int s=h;
    float m=bm[s], pv=bv[s];
    for(int k=0;k<64;k++){ m=fmaf(Wm[s*64+k],myh[k],m); pv=fmaf(Wv[s*64+k],myh[k],pv); }
    float v=fmaxf(pv,0.f)+log1pf(expf(-fabsf(pv)))+1e-6f;
    g_m0[b*4+s]=m; g_v0[b*4+s]=v;
    atomicAdd(&g_acc[0],0.5*(double)(v+m*m-1.f-logf(v)));
  }
}

// ---- fused 4-layer MLP -> par, 32-row tiles ----
__global__ void __launch_bounds__(256) k_mlp(const float* obs,
  const float* W1,const float* b1,const float* W2,const float* b2,
  const float* W3,const float* b3,const float* W4,const float* b4){
  extern __shared__ __align__(16) float sm[];
  float* W2s=sm;                    // 128*260
  float* W3s=W2s+128*260;           // 64*132
  float* W4s=W3s+64*132;            // 36*68
  float* W1s=W4s+36*68;             // 256*3
  float* b1s=W1s+768; float* b2s=b1s+256; float* b3s=b2s+128; float* b4s=b3s+64;
  float* h1t=b4s+36;                // 32*260 (reused as h3t, stride 68)
  float* h2t=h1t+32*260;            // 32*132
  int tid=threadIdx.x;
  for(int i=tid;i<128*256;i+=256) W2s[(i>>8)*260+(i&255)]=W2[i];
  for(int i=tid;i<64*128;i+=256)  W3s[(i>>7)*132+(i&127)]=W3[i];
  for(int i=tid;i<36*64;i+=256)   W4s[(i>>6)*68+(i&63)]=W4[i];
  if(tid<256){ W1s[tid*3]=W1[tid*3]; W1s[tid*3+1]=W1[tid*3+1]; W1s[tid*3+2]=W1[tid*3+2]; b1s[tid]=b1[tid]; }
  if(tid<128) b2s[tid]=b2[tid];
  if(tid<64)  b3s[tid]=b3[tid];
  if(tid<36)  b4s[tid]=b4[tid];
  __syncthreads();
  int rb=blockIdx.x*128;
  for(int tile=0;tile<4;tile++){
    int r0=rb+tile*32;
    for(int i=tid;i<32*256;i+=256){
      int r=i>>8, j=i&255, row=r0+r;
      float a=b1s[j]+W1s[j*3]*obs[row*3]+W1s[j*3+1]*obs[row*3+1]+W1s[j*3+2]*obs[row*3+2];
      h1t[r*260+j]=fmaxf(a,0.f);
    }
    __syncthreads();
    for(int i=tid;i<32*128;i+=256){
      int r=i>>7, j=i&127;
      float a=b2s[j];
      const float4* w=(const float4*)(W2s+j*260);
      const float4* hv=(const float4*)(h1t+r*260);
      #pragma unroll 8
      for(int k=0;k<64;k++){ float4 wv=w[k],h4=hv[k];
        a=fmaf(wv.x,h4.x,a); a=fmaf(wv.y,h4.y,a); a=fmaf(wv.z,h4.z,a); a=fmaf(wv.w,h4.w,a); }
      h2t[r*132+j]=fmaxf(a,0.f);
    }
    __syncthreads();
    for(int i=tid;i<32*64;i+=256){
      int r=i>>6, j=i&63;
      float a=b3s[j];
      const float4* w=(const float4*)(W3s+j*132);
      const float4* hv=(const float4*)(h2t+r*132);
      #pragma unroll 8
      for(int k=0;k<32;k++){ float4 wv=w[k],h4=hv[k];
        a=fmaf(wv.x,h4.x,a); a=fmaf(wv.y,h4.y,a); a=fmaf(wv.z,h4.z,a); a=fmaf(wv.w,h4.w,a); }
      h1t[r*68+j]=fmaxf(a,0.f);
    }
    __syncthreads();
    for(int i=tid;i<32*36;i+=256){
      int r=i/36, j=i%36;
      float a=b4s[j];
      const float4* w=(const float4*)(W4s+j*68);
      const float4* hv=(const float4*)(h1t+r*68);
      #pragma unroll
      for(int k=0;k<16;k++){ float4 wv=w[k],h4=hv[k];
        a=fmaf(wv.x,h4.x,a); a=fmaf(wv.y,h4.y,a); a=fmaf(wv.z,h4.z,a); a=fmaf(wv.w,h4.w,a); }
      g_par[(r0+r)*36+j]=a;
    }
    __syncthreads();
  }
}

// ---- main scan: warp per (n,b) chain, 128 steps ----
__global__ void __launch_bounds__(256) k_step(const float* Z,const float* lls,
    const float* los,const float* npc,const float* nem,const float* obs){
  __shared__ __align__(16) float Cs[4608];
  __shared__ __align__(16) float kb[8][132];   // per warp: kx[d*32+l]
  int tid=threadIdx.x, wid=tid>>5, l=tid&31;
  unsigned FM=0xffffffffu;
  for(int i=tid;i<4608;i+=256) Cs[i]=g_C[i];
  int c=blockIdx.x*8+wid;
  int n=c>>8, b=c&255;
  float zl[4][4], il[4][4], osd[4], ul[4], np_[4], ine[3];
  #pragma unroll
  for(int d=0;d<4;d++){
    osd[d]=expf(los[d]); np_[d]=npc[d];
    ul[d]=g_u[(n*4+d)*32+l];
    #pragma unroll
    for(int k=0;k<4;k++){ il[d][k]=expf(-lls[d*4+k]); zl[d][k]=Z[(d*32+l)*4+k]; }
  }
  float cterm=0.f;
  #pragma unroll
  for(int o=0;o<3;o++){ ine[o]=1.f/nem[o]; cterm+=LOG2PI_F+logf(nem[o]); }
  float x[4][4];
  #pragma unroll
  for(int d=0;d<4;d++)
    #pragma unroll
    for(int k=0;k<4;k++)
      x[d][k]=g_m0[b*4+k]+sqrtf(g_v0[b*4+k])*g_eps0[((n*4+d)*256+b)*4+k];
  __syncthreads();
  double klacc=0.0, likacc=0.0;
  for(int t=0;t<128;t++){
    // kxz for all 4 dims, then one smem exchange
    float kx[4];
    #pragma unroll
    for(int d=0;d<4;d++){
      float s=0.f;
      #pragma unroll
      for(int k=0;k<4;k++){ float df=(x[d][k]-zl[d][k])*il[d][k]; s=fmaf(df,df,s); }
      kx[d]=osd[d]*expf(-0.5f*s);
    }
    __syncwarp();
    #pragma unroll
    for(int d=0;d<4;d++) kb[wid][d*32+l]=kx[d];
    __syncwarp();
    float pm[4], pv[4];
    #pragma unroll
    for(int d=0;d<4;d++){
      float w=0.f;
      const float4* Crow=(const float4*)(Cs+d*1152+l*36);
      const float4* kq=(const float4*)(kb[wid]+d*32);
      #pragma unroll
      for(int j=0;j<8;j++){
        if(j*4<=l){
          float4 cv=Crow[j], kv=kq[j];
          w=fmaf(cv.x,kv.x,w); w=fmaf(cv.y,kv.y,w);
          w=fmaf(cv.z,kv.z,w); w=fmaf(cv.w,kv.w,w);
        }
      }
      pm[d]=w*ul[d]; pv[d]=w*w;
    }
    #pragma unroll
    for(int o=16;o;o>>=1){
      #pragma unroll
      for(int d=0;d<4;d++){
        pm[d]+=__shfl_xor_sync(FM,pm[d],o);
        pv[d]+=__shfl_xor_sync(FM,pv[d],o);
      }
    }
    float gm[4], gv[4];
    #pragma unroll
    for(int d=0;d<4;d++){ gm[d]=pm[d]; gv[d]=fmaxf(osd[d]-pv[d],1e-8f); }
    const float* pr=g_par+(b*128+t)*36;
    float Atm[16], btv[4], Sl[16];
    #pragma unroll
    for(int i=0;i<16;i++) Atm[i]=pr[i];
    #pragma unroll
    for(int i=0;i<4;i++) btv[i]=pr[16+i];
    #pragma unroll
    for(int i=0;i<16;i++) Sl[i]=((i&3)<=(i>>2))?pr[20+i]:0.f;
    float qm[4];
    #pragma unroll
    for(int i=0;i<4;i++){
      float s=btv[i];
      #pragma unroll
      for(int j=0;j<4;j++) s=fmaf(Atm[i*4+j],gm[j],s);
      qm[i]=s;
    }
    float qc[16];
    #pragma unroll
    for(int i=0;i<4;i++)
      #pragma unroll
      for(int k2=0;k2<4;k2++){
        if(k2>i) continue;
        float s=0.f;
        #pragma unroll
        for(int j=0;j<4;j++) s=fmaf(Sl[i*4+j],Sl[k2*4+j],s);
        #pragma unroll
        for(int j=0;j<4;j++) s=fmaf(Atm[i*4+j]*gv[j],Atm[k2*4+j],s);
        qc[i*4+k2]=s; qc[k2*4+i]=s;
      }
    float l00=sqrtf(qc[0]+1e-6f), i0=1.f/l00;
    float l10=qc[4]*i0, l20=qc[8]*i0, l30=qc[12]*i0;
    float l11=sqrtf(qc[5]+1e-6f-l10*l10), i1=1.f/l11;
    float l21=(qc[9]-l20*l10)*i1, l31=(qc[13]-l30*l10)*i1;
    float l22=sqrtf(qc[10]+1e-6f-l20*l20-l21*l21), i2=1.f/l22;
    float l32=(qc[14]-l30*l20-l31*l21)*i2;
    float l33=sqrtf(qc[15]+1e-6f-l30*l30-l31*l31-l32*l32);
    // kl: single log of ratio of products
    float kl=0.f, prodd0=1.f;
    #pragma unroll
    for(int i=0;i<4;i++){
      float d0=gv[i]+np_[i];
      float df=gm[i]-qm[i];
      kl+=(qc[i*4+i]+df*df)/d0;
      prodd0*=d0;
    }
    float pl=l00*l11*l22*l33;
    kl=0.5f*(kl-4.f+logf(prodd0/(pl*pl)));
    float el=cterm;
    #pragma unroll
    for(int o=0;o<3;o++){
      float y=obs[(b*128+t)*3+o];
      float r=y-qm[o];
      el=fmaf(r*r+qc[o*4+o],ine[o],el);
    }
    el=-0.5f*el;
    klacc+=(double)kl; likacc+=(double)el;
    const float* ep=g_epsq+((t*16+n)*256+b)*4;
    float e0=ep[0],e1=ep[1],e2=ep[2],e3=ep[3];
    float xn0=qm[0]+l00*e0;
    float xn1=qm[1]+l10*e0+l11*e1;
    float xn2=qm[2]+l20*e0+l21*e1+l22*e2;
    float xn3=qm[3]+l30*e0+l31*e1+l32*e2+l33*e3;
    #pragma unroll
    for(int d=0;d<4;d++){ x[d][0]=xn0; x[d][1]=xn1; x[d][2]=xn2; x[d][3]=xn3; }
  }
  if(l==0){
    atomicAdd(&g_acc[2],klacc);
    atomicAdd(&g_acc[3],likacc);
  }
}

__global__ void k_fin(float* out){
  double qm0=g_acc[0]/256.0, gpKL=g_acc[1];
  double KL=g_acc[2]/4096.0, lik=g_acc[3]/4096.0;
  double E=-qm0-gpKL+lik-KL;
  if(lik>KL) E=-qm0-gpKL+lik/128.0-KL;
  out[0]=(float)E;
}

extern "C" void kernel_launch(void* const* d_in, const int* in_sizes, int n_in,
                              void* d_out, int out_size){
  const float* obs=(const float*)d_in[0];
  const float* Z  =(const float*)d_in[1];
  const float* lls=(const float*)d_in[2];
  const float* los=(const float*)d_in[3];
  const float* m_u=(const float*)d_in[4];
  const float* Lu =(const float*)d_in[5];
  const float* npc=(const float*)d_in[6];
  const float* nem=(const float*)d_in[7];
  const float* Wih=(const float*)d_in[8];
  const float* Whh=(const float*)d_in[9];
  const float* bl =(const float*)d_in[10];
  const float* Wm =(const float*)d_in[11];
  const float* bm =(const float*)d_in[12];
  const float* Wv =(const float*)d_in[13];
  const float* bv =(const float*)d_in[14];
  const float* W1 =(const float*)d_in[15];
  const float* b1 =(const float*)d_in[16];
  const float* W2 =(const float*)d_in[17];
  const float* b2 =(const float*)d_in[18];
  const float* W3 =(const float*)d_in[19];
  const float* b3 =(const float*)d_in[20];
  const float* W4 =(const float*)d_in[21];
  const float* b4 =(const float*)d_in[22];

  // _threefry_split_foldlike: subkey_i = full pair of threefry(key, hi=0, lo=i)
  uint32_t K0a,K0b,KUa,KUb,KQa,KQb;
  tf2x32(0u,42u,0u,0u,K0a,K0b);
  tf2x32(0u,42u,0u,1u,KUa,KUb);
  tf2x32(0u,42u,0u,2u,KQa,KQb);

  cudaFuncSetAttribute(k_lstm, cudaFuncAttributeMaxDynamicSharedMemorySize, 79392);
  cudaFuncSetAttribute(k_mlp,  cudaFuncAttributeMaxDynamicSharedMemorySize, 231888);

  k_prng_all<<<8457,256>>>(K0a,K0b,KUa,KUb,KQa,KQb);     // launch 0
  k_prep<<<1,128>>>(Z,lls,los,m_u,Lu);                   // launch 1
  k_uprep<<<2,1024>>>(m_u,Lu);                           // launch 2
  k_lstm<<<128,128,79392>>>(obs,Wih,Whh,bl,Wm,bm,Wv,bv); // launch 3
  k_mlp<<<256,256,231888>>>(obs,W1,b1,W2,b2,W3,b3,W4,b4);// launch 4
  k_step<<<512,256>>>(Z,lls,los,npc,nem,obs);            // launch 5  (ncu -s 5 lands here)
  k_fin<<<1,1>>>((float*)d_out);                         // launch 6
}

// round 15
// speedup vs baseline: 1.3000x; 1.0017x over previous
#include <cuda_runtime.h>
#include <cstdint>

#define LOG2PI_F 1.8378770664093453f

__device__ double g_acc[4];                 // 0 qm0, 1 gpKL, 2 KL, 3 lik
__device__ float g_eps0[16*4*256*4];
__device__ float g_epsU[16*4*32];
__device__ float g_epsq[128*16*256*4];
__device__ float g_m0[256*4];
__device__ float g_v0[256*4];
__device__ float g_C[4*32*36];              // Lzz^-1, zero-padded rows of 36
__device__ float g_u[16*4*32];              // u' = C @ U
__device__ float g_par[256*128*36];

__host__ __device__ inline void tf2x32(uint32_t k0,uint32_t k1,uint32_t c0,uint32_t c1,
                                       uint32_t &o0,uint32_t &o1){
  uint32_t ks[3]={k0,k1,k0^k1^0x1BD11BDAu};
  uint32_t x0=c0+ks[0], x1=c1+ks[1];
  const int rA[4]={13,15,26,6}, rB[4]={17,29,16,24};
  for(int i=0;i<5;i++){
    const int* rr=(i&1)?rB:rA;
    for(int j=0;j<4;j++){ x0+=x1; int d=rr[j]; x1=(x1<<d)|(x1>>(32-d)); x1^=x0; }
    x0+=ks[(i+1)%3]; x1+=ks[(i+2)%3]+(uint32_t)(i+1);
  }
  o0=x0; o1=x1;
}

__device__ inline float erfinv_f(float x){
  float w=-log1pf(-x*x), p;
  if(w<5.0f){
    w-=2.5f;
    p=2.81022636e-08f;           p=fmaf(p,w,3.43273939e-07f);
    p=fmaf(p,w,-3.5233877e-06f); p=fmaf(p,w,-4.39150654e-06f);
    p=fmaf(p,w,0.00021858087f);  p=fmaf(p,w,-0.00125372503f);
    p=fmaf(p,w,-0.00417768164f); p=fmaf(p,w,0.246640727f);
    p=fmaf(p,w,1.50140941f);
  }else{
    w=sqrtf(w)-3.0f;
    p=-0.000200214257f;          p=fmaf(p,w,0.000100950558f);
    p=fmaf(p,w,0.00134934322f);  p=fmaf(p,w,-0.00367342844f);
    p=fmaf(p,w,0.00573950773f);  p=fmaf(p,w,-0.0076224613f);
    p=fmaf(p,w,0.00943887047f);  p=fmaf(p,w,1.00167406f);
    p=fmaf(p,w,2.83297682f);
  }
  return p*x;
}

__device__ inline float b2n(uint32_t bits){
  float f=__uint_as_float((bits>>9)|0x3f800000u)-1.0f;
  const float lo=-0.99999994f;
  float u=fmaxf(lo, f*2.0f+lo);
  return 1.41421356237f*erfinv_f(u);
}

// ---- all PRNG streams + accumulator zeroing in ONE launch ----
// segments: [0,65536) eps0 | [65536,67584) epsU | [67584,2164736) epsq
__global__ void k_prng_all(uint32_t K0a,uint32_t K0b,uint32_t KUa,uint32_t KUb,
                           uint32_t KQa,uint32_t KQb){
  int j=blockIdx.x*blockDim.x+threadIdx.x;
  if(j<4) g_acc[j]=0.0;
  if(j>=2164736) return;
  uint32_t ka,kb; float* out; int lj;
  if(j<65536){ ka=K0a; kb=K0b; out=g_eps0; lj=j; }
  else if(j<67584){ ka=KUa; kb=KUb; out=g_epsU; lj=j-65536; }
  else { ka=KQa; kb=KQb; out=g_epsq; lj=j-67584; }
  uint32_t a,b; tf2x32(ka,kb,0u,(uint32_t)lj,a,b);
  out[lj]=b2n(a^b);
}

// ---- Kzz, Cholesky, C = L^-1, gpKL ----
__global__ void k_prep(const float* Z,const float* lls,const float* los,
                       const float* m_u,const float* Lu){
  __shared__ float A[4][1056], Cs[4][1056];
  int d=threadIdx.x>>5, l=threadIdx.x&31;
  unsigned FM=0xffffffffu;
  float il[4], zl[4];
  for(int k=0;k<4;k++){ il[k]=expf(-lls[d*4+k]); zl[k]=Z[(d*32+l)*4+k]; }
  float osd=expf(los[d]);
  for(int i=0;i<32;i++){
    float s=0;
    for(int k=0;k<4;k++){ float df=(Z[(d*32+i)*4+k]-zl[k])*il[k]; s+=df*df; }
    A[d][i*33+l]=osd*expf(-0.5f*s)+((i==l)?1e-5f:0.f);
  }
  __syncwarp();
  for(int j=0;j<32;j++){
    float s=0.f;
    if(l>=j){ s=A[d][l*33+j]; for(int k=0;k<j;k++) s-=A[d][l*33+k]*A[d][j*33+k]; }
    float dj=sqrtf(__shfl_sync(FM,s,j));
    if(l==j) A[d][l*33+j]=dj; else if(l>j) A[d][l*33+j]=s/dj;
    __syncwarp();
  }
  for(int i=0;i<32;i++){
    float s=(i==l)?1.f:0.f;
    for(int k=l;k<i;k++) s-=A[d][i*33+k]*Cs[d][k*33+l];
    Cs[d][i*33+l]=(i>=l)?s/A[d][i*33+i]:0.f;
    __syncwarp();
  }
  for(int idx=l; idx<32*36; idx+=32){
    int m=idx/36, j=idx%36;
    g_C[d*1152+idx]=(j<32&&j<=m)?Cs[d][m*33+j]:0.f;
  }
  float accA=0.f;
  for(int i=0;i<32;i++){
    float a=0.f;
    for(int j=l;j<=i;j++) a+=Cs[d][i*33+j]*Lu[(d*32+j)*32+l];
    accA+=a*a;
  }
  float bq;
  { float s=0.f; for(int j=0;j<=l;j++) s+=Cs[d][l*33+j]*m_u[d*32+j]; bq=s*s; }
  float ldK=2.f*logf(A[d][l*33+l]);
  float ldS=2.f*logf(fabsf(Lu[(d*32+l)*32+l])+1e-12f);
  float tot=accA+bq-1.f+ldK-ldS;
  for(int o=16;o;o>>=1) tot+=__shfl_xor_sync(FM,tot,o);
  if(l==0) atomicAdd(&g_acc[1],0.5*(double)tot/(128.0*256.0));
}

// ---- U = m_u + tril(Lu) epsU ; u' = C U ----
__global__ void k_uprep(const float* m_u,const float* Lu){
  int gt=blockIdx.x*blockDim.x+threadIdx.x;
  int w=gt>>5, l=gt&31;
  if(w>=64) return;
  int n=w>>2, d=w&3;
  unsigned FM=0xffffffffu;
  float e=g_epsU[(n*4+d)*32+l];
  float U=m_u[d*32+l];
  for(int k=0;k<32;k++){
    float ek=__shfl_sync(FM,e,k);
    float lv=(k<=l)?Lu[(d*32+l)*32+k]:0.f;
    U=fmaf(lv,ek,U);
  }
  float s=0.f;
  for(int j=0;j<32;j++){
    float Uj=__shfl_sync(FM,U,j);
    s=fmaf(g_C[d*1152+l*36+j],Uj,s);
  }
  g_u[(n*4+d)*32+l]=s;
}

__device__ inline float sigf(float x){ return 1.f/(1.f+expf(-x)); }

// ---- LSTM encoder: 2 batches per block, float4 inner loop ----
__global__ void __launch_bounds__(128) k_lstm(const float* obs,const float* Wih,
    const float* Whh,const float* bl,const float* Wm,const float* bm,
    const float* Wv,const float* bv){
  extern __shared__ __align__(16) float sm[];
  float* whh=sm;               // 256*68 (stride 68, float4-aligned, conflict-free)
  float* wih=whh+256*68;       // 256*4
  float* bb =wih+1024;         // 256
  float* ob =bb+256;           // 2*128*4
  float* hs =ob+1024;          // 2*68
  int tid=threadIdx.x, g=tid>>6, h=tid&63;
  for(int idx=tid; idx<256*64; idx+=128){ int r=idx>>6,c2=idx&63; whh[r*68+c2]=Whh[idx]; }
  for(int idx=tid; idx<256; idx+=128){
    wih[idx*4]=Wih[idx*3]; wih[idx*4+1]=Wih[idx*3+1]; wih[idx*4+2]=Wih[idx*3+2];
    bb[idx]=bl[idx];
  }
  for(int idx=tid; idx<2*128*3; idx+=128){
    int gg=idx/384, rem=idx%384, t=rem/3, c2=rem%3;
    ob[(gg*128+t)*4+c2]=obs[((blockIdx.x*2+gg)*128+t)*3+c2];
  }
  hs[g*68+h]=0.f;
  __syncthreads();
  float c=0.f;
  int ri=h, rf=64+h, rg=128+h, ro=192+h;
  const float* myob=ob+g*512;
  float* myh=hs+g*68;
  int b=blockIdx.x*2+g;
  for(int t=0;t<128;t++){
    float x0=myob[t*4], x1=myob[t*4+1], x2=myob[t*4+2];
    float gi=bb[ri]+wih[ri*4]*x0+wih[ri*4+1]*x1+wih[ri*4+2]*x2;
    float gf=bb[rf]+wih[rf*4]*x0+wih[rf*4+1]*x1+wih[rf*4+2]*x2;
    float gg=bb[rg]+wih[rg*4]*x0+wih[rg*4+1]*x1+wih[rg*4+2]*x2;
    float go=bb[ro]+wih[ro*4]*x0+wih[ro*4+1]*x1+wih[ro*4+2]*x2;
    #pragma unroll 4
    for(int k=0;k<64;k+=4){
      float4 h4=*(const float4*)(myh+k);
      float4 wA=*(const float4*)(whh+ri*68+k);
      float4 wB=*(const float4*)(whh+rf*68+k);
      float4 wC=*(const float4*)(whh+rg*68+k);
      float4 wD=*(const float4*)(whh+ro*68+k);
      gi=fmaf(wA.x,h4.x,gi); gi=fmaf(wA.y,h4.y,gi); gi=fmaf(wA.z,h4.z,gi); gi=fmaf(wA.w,h4.w,gi);
      gf=fmaf(wB.x,h4.x,gf); gf=fmaf(wB.y,h4.y,gf); gf=fmaf(wB.z,h4.z,gf); gf=fmaf(wB.w,h4.w,gf);
      gg=fmaf(wC.x,h4.x,gg); gg=fmaf(wC.y,h4.y,gg); gg=fmaf(wC.z,h4.z,gg); gg=fmaf(wC.w,h4.w,gg);
      go=fmaf(wD.x,h4.x,go); go=fmaf(wD.y,h4.y,go); go=fmaf(wD.z,h4.z,go); go=fmaf(wD.w,h4.w,go);
    }
    c=sigf(gf)*c+sigf(gi)*tanhf(gg);
    float hn=sigf(go)*tanhf(c);
    __syncthreads();
    myh[h]=hn;
    __syncthreads();
  }
  if(h<4){
    int s=h;
    float m=bm[s], pv=bv[s];
    for(int k=0;k<64;k++){ m=fmaf(Wm[s*64+k],myh[k],m); pv=fmaf(Wv[s*64+k],myh[k],pv); }
    float v=fmaxf(pv,0.f)+log1pf(expf(-fabsf(pv)))+1e-6f;
    g_m0[b*4+s]=m; g_v0[b*4+s]=v;
    atomicAdd(&g_acc[0],0.5*(double)(v+m*m-1.f-logf(v)));
  }
}

// ---- fused 4-layer MLP -> par, 32-row tiles ----
__global__ void __launch_bounds__(256) k_mlp(const float* obs,
  const float* W1,const float* b1,const float* W2,const float* b2,
  const float* W3,const float* b3,const float* W4,const float* b4){
  extern __shared__ __align__(16) float sm[];
  float* W2s=sm;                    // 128*260
  float* W3s=W2s+128*260;           // 64*132
  float* W4s=W3s+64*132;            // 36*68
  float* W1s=W4s+36*68;             // 256*3
  float* b1s=W1s+768; float* b2s=b1s+256; float* b3s=b2s+128; float* b4s=b3s+64;
  float* h1t=b4s+36;                // 32*260 (reused as h3t, stride 68)
  float* h2t=h1t+32*260;            // 32*132
  int tid=threadIdx.x;
  for(int i=tid;i<128*256;i+=256) W2s[(i>>8)*260+(i&255)]=W2[i];
  for(int i=tid;i<64*128;i+=256)  W3s[(i>>7)*132+(i&127)]=W3[i];
  for(int i=tid;i<36*64;i+=256)   W4s[(i>>6)*68+(i&63)]=W4[i];
  if(tid<256){ W1s[tid*3]=W1[tid*3]; W1s[tid*3+1]=W1[tid*3+1]; W1s[tid*3+2]=W1[tid*3+2]; b1s[tid]=b1[tid]; }
  if(tid<128) b2s[tid]=b2[tid];
  if(tid<64)  b3s[tid]=b3[tid];
  if(tid<36)  b4s[tid]=b4[tid];
  __syncthreads();
  int rb=blockIdx.x*128;
  for(int tile=0;tile<4;tile++){
    int r0=rb+tile*32;
    for(int i=tid;i<32*256;i+=256){
      int r=i>>8, j=i&255, row=r0+r;
      float a=b1s[j]+W1s[j*3]*obs[row*3]+W1s[j*3+1]*obs[row*3+1]+W1s[j*3+2]*obs[row*3+2];
      h1t[r*260+j]=fmaxf(a,0.f);
    }
    __syncthreads();
    for(int i=tid;i<32*128;i+=256){
      int r=i>>7, j=i&127;
      float a=b2s[j];
      const float4* w=(const float4*)(W2s+j*260);
      const float4* hv=(const float4*)(h1t+r*260);
      #pragma unroll 8
      for(int k=0;k<64;k++){ float4 wv=w[k],h4=hv[k];
        a=fmaf(wv.x,h4.x,a); a=fmaf(wv.y,h4.y,a); a=fmaf(wv.z,h4.z,a); a=fmaf(wv.w,h4.w,a); }
      h2t[r*132+j]=fmaxf(a,0.f);
    }
    __syncthreads();
    for(int i=tid;i<32*64;i+=256){
      int r=i>>6, j=i&63;
      float a=b3s[j];
      const float4* w=(const float4*)(W3s+j*132);
      const float4* hv=(const float4*)(h2t+r*132);
      #pragma unroll 8
      for(int k=0;k<32;k++){ float4 wv=w[k],h4=hv[k];
        a=fmaf(wv.x,h4.x,a); a=fmaf(wv.y,h4.y,a); a=fmaf(wv.z,h4.z,a); a=fmaf(wv.w,h4.w,a); }
      h1t[r*68+j]=fmaxf(a,0.f);
    }
    __syncthreads();
    for(int i=tid;i<32*36;i+=256){
      int r=i/36, j=i%36;
      float a=b4s[j];
      const float4* w=(const float4*)(W4s+j*68);
      const float4* hv=(const float4*)(h1t+r*68);
      #pragma unroll
      for(int k=0;k<16;k++){ float4 wv=w[k],h4=hv[k];
        a=fmaf(wv.x,h4.x,a); a=fmaf(wv.y,h4.y,a); a=fmaf(wv.z,h4.z,a); a=fmaf(wv.w,h4.w,a); }
      g_par[(r0+r)*36+j]=a;
    }
    __syncthreads();
  }
}

// ---- main scan: warp per (n,b) chain, 128 steps ----
__global__ void __launch_bounds__(256) k_step(const float* Z,const float* lls,
    const float* los,const float* npc,const float* nem,const float* obs){
  __shared__ __align__(16) float Cs[4608];
  __shared__ __align__(16) float kb[8][132];   // per warp: kx[d*32+l]
  int tid=threadIdx.x, wid=tid>>5, l=tid&31;
  unsigned FM=0xffffffffu;
  for(int i=tid;i<4608;i+=256) Cs[i]=g_C[i];
  int c=blockIdx.x*8+wid;
  int n=c>>8, b=c&255;
  float zl[4][4], il[4][4], osd[4], ul[4], np_[4], ine[3];
  #pragma unroll
  for(int d=0;d<4;d++){
    osd[d]=expf(los[d]); np_[d]=npc[d];
    ul[d]=g_u[(n*4+d)*32+l];
    #pragma unroll
    for(int k=0;k<4;k++){ il[d][k]=expf(-lls[d*4+k]); zl[d][k]=Z[(d*32+l)*4+k]; }
  }
  float cterm=0.f;
  #pragma unroll
  for(int o=0;o<3;o++){ ine[o]=1.f/nem[o]; cterm+=LOG2PI_F+logf(nem[o]); }
  float x[4][4];
  #pragma unroll
  for(int d=0;d<4;d++)
    #pragma unroll
    for(int k=0;k<4;k++)
      x[d][k]=g_m0[b*4+k]+sqrtf(g_v0[b*4+k])*g_eps0[((n*4+d)*256+b)*4+k];
  __syncthreads();
  double klacc=0.0, likacc=0.0;
  for(int t=0;t<128;t++){
    // kxz for all 4 dims, then one smem exchange
    float kx[4];
    #pragma unroll
    for(int d=0;d<4;d++){
      float s=0.f;
      #pragma unroll
      for(int k=0;k<4;k++){ float df=(x[d][k]-zl[d][k])*il[d][k]; s=fmaf(df,df,s); }
      kx[d]=osd[d]*expf(-0.5f*s);
    }
    __syncwarp();
    #pragma unroll
    for(int d=0;d<4;d++) kb[wid][d*32+l]=kx[d];
    __syncwarp();
    float pm[4], pv[4];
    #pragma unroll
    for(int d=0;d<4;d++){
      float w=0.f;
      const float4* Crow=(const float4*)(Cs+d*1152+l*36);
      const float4* kq=(const float4*)(kb[wid]+d*32);
      #pragma unroll
      for(int j=0;j<8;j++){
        if(j*4<=l){
          float4 cv=Crow[j], kv=kq[j];
          w=fmaf(cv.x,kv.x,w); w=fmaf(cv.y,kv.y,w);
          w=fmaf(cv.z,kv.z,w); w=fmaf(cv.w,kv.w,w);
        }
      }
      pm[d]=w*ul[d]; pv[d]=w*w;
    }
    #pragma unroll
    for(int o=16;o;o>>=1){
      #pragma unroll
      for(int d=0;d<4;d++){
        pm[d]+=__shfl_xor_sync(FM,pm[d],o);
        pv[d]+=__shfl_xor_sync(FM,pv[d],o);
      }
    }
    float gm[4], gv[4];
    #pragma unroll
    for(int d=0;d<4;d++){ gm[d]=pm[d]; gv[d]=fmaxf(osd[d]-pv[d],1e-8f); }
    const float* pr=g_par+(b*128+t)*36;
    float Atm[16], btv[4], Sl[16];
    #pragma unroll
    for(int i=0;i<16;i++) Atm[i]=pr[i];
    #pragma unroll
    for(int i=0;i<4;i++) btv[i]=pr[16+i];
    #pragma unroll
    for(int i=0;i<16;i++) Sl[i]=((i&3)<=(i>>2))?pr[20+i]:0.f;
    float qm[4];
    #pragma unroll
    for(int i=0;i<4;i++){
      float s=btv[i];
      #pragma unroll
      for(int j=0;j<4;j++) s=fmaf(Atm[i*4+j],gm[j],s);
      qm[i]=s;
    }
    float qc[16];
    #pragma unroll
    for(int i=0;i<4;i++)
      #pragma unroll
      for(int k2=0;k2<4;k2++){
        if(k2>i) continue;
        float s=0.f;
        #pragma unroll
        for(int j=0;j<4;j++) s=fmaf(Sl[i*4+j],Sl[k2*4+j],s);
        #pragma unroll
        for(int j=0;j<4;j++) s=fmaf(Atm[i*4+j]*gv[j],Atm[k2*4+j],s);
        qc[i*4+k2]=s; qc[k2*4+i]=s;
      }
    float l00=sqrtf(qc[0]+1e-6f), i0=1.f/l00;
    float l10=qc[4]*i0, l20=qc[8]*i0, l30=qc[12]*i0;
    float l11=sqrtf(qc[5]+1e-6f-l10*l10), i1=1.f/l11;
    float l21=(qc[9]-l20*l10)*i1, l31=(qc[13]-l30*l10)*i1;
    float l22=sqrtf(qc[10]+1e-6f-l20*l20-l21*l21), i2=1.f/l22;
    float l32=(qc[14]-l30*l20-l31*l21)*i2;
    float l33=sqrtf(qc[15]+1e-6f-l30*l30-l31*l31-l32*l32);
    // kl: single log of ratio of products
    float kl=0.f, prodd0=1.f;
    #pragma unroll
    for(int i=0;i<4;i++){
      float d0=gv[i]+np_[i];
      float df=gm[i]-qm[i];
      kl+=(qc[i*4+i]+df*df)/d0;
      prodd0*=d0;
    }
    float pl=l00*l11*l22*l33;
    kl=0.5f*(kl-4.f+logf(prodd0/(pl*pl)));
    float el=cterm;
    #pragma unroll
    for(int o=0;o<3;o++){
      float y=obs[(b*128+t)*3+o];
      float r=y-qm[o];
      el=fmaf(r*r+qc[o*4+o],ine[o],el);
    }
    el=-0.5f*el;
    klacc+=(double)kl; likacc+=(double)el;
    const float* ep=g_epsq+((t*16+n)*256+b)*4;
    float e0=ep[0],e1=ep[1],e2=ep[2],e3=ep[3];
    float xn0=qm[0]+l00*e0;
    float xn1=qm[1]+l10*e0+l11*e1;
    float xn2=qm[2]+l20*e0+l21*e1+l22*e2;
    float xn3=qm[3]+l30*e0+l31*e1+l32*e2+l33*e3;
    #pragma unroll
    for(int d=0;d<4;d++){ x[d][0]=xn0; x[d][1]=xn1; x[d][2]=xn2; x[d][3]=xn3; }
  }
  if(l==0){
    atomicAdd(&g_acc[2],klacc);
    atomicAdd(&g_acc[3],likacc);
  }
}

__global__ void k_fin(float* out){
  double qm0=g_acc[0]/256.0, gpKL=g_acc[1];
  double KL=g_acc[2]/4096.0, lik=g_acc[3]/4096.0;
  double E=-qm0-gpKL+lik-KL;
  if(lik>KL) E=-qm0-gpKL+lik/128.0-KL;
  out[0]=(float)E;
}

extern "C" void kernel_launch(void* const* d_in, const int* in_sizes, int n_in,
                              void* d_out, int out_size){
  const float* obs=(const float*)d_in[0];
  const float* Z  =(const float*)d_in[1];
  const float* lls=(const float*)d_in[2];
  const float* los=(const float*)d_in[3];
  const float* m_u=(const float*)d_in[4];
  const float* Lu =(const float*)d_in[5];
  const float* npc=(const float*)d_in[6];
  const float* nem=(const float*)d_in[7];
  const float* Wih=(const float*)d_in[8];
  const float* Whh=(const float*)d_in[9];
  const float* bl =(const float*)d_in[10];
  const float* Wm =(const float*)d_in[11];
  const float* bm =(const float*)d_in[12];
  const float* Wv =(const float*)d_in[13];
  const float* bv =(const float*)d_in[14];
  const float* W1 =(const float*)d_in[15];
  const float* b1 =(const float*)d_in[16];
  const float* W2 =(const float*)d_in[17];
  const float* b2 =(const float*)d_in[18];
  const float* W3 =(const float*)d_in[19];
  const float* b3 =(const float*)d_in[20];
  const float* W4 =(const float*)d_in[21];
  const float* b4 =(const float*)d_in[22];

  // _threefry_split_foldlike: subkey_i = full pair of threefry(key, hi=0, lo=i)
  uint32_t K0a,K0b,KUa,KUb,KQa,KQb;
  tf2x32(0u,42u,0u,0u,K0a,K0b);
  tf2x32(0u,42u,0u,1u,KUa,KUb);
  tf2x32(0u,42u,0u,2u,KQa,KQb);

  cudaFuncSetAttribute(k_lstm, cudaFuncAttributeMaxDynamicSharedMemorySize, 79392);
  cudaFuncSetAttribute(k_mlp,  cudaFuncAttributeMaxDynamicSharedMemorySize, 231888);

  k_prng_all<<<8457,256>>>(K0a,K0b,KUa,KUb,KQa,KQb);     // launch 0
  k_prep<<<1,128>>>(Z,lls,los,m_u,Lu);                   // launch 1
  k_uprep<<<2,1024>>>(m_u,Lu);                           // launch 2
  k_lstm<<<128,128,79392>>>(obs,Wih,Whh,bl,Wm,bm,Wv,bv); // launch 3
  k_mlp<<<256,256,231888>>>(obs,W1,b1,W2,b2,W3,b3,W4,b4);// launch 4
  k_step<<<512,256>>>(Z,lls,los,npc,nem,obs);            // launch 5  (ncu -s 5 lands here)
  k_fin<<<1,1>>>((float*)d_out);                         // launch 6
}

// round 16
// speedup vs baseline: 1.4167x; 1.0898x over previous
#include <cuda_runtime.h>
#include <cstdint>

#define LOG2PI_F 1.8378770664093453f

__device__ double g_acc[4];
__device__ float g_eps0[16*4*256*4];
__device__ float g_epsU[16*4*32];
__device__ float g_epsq[128*16*256*4];
__device__ float g_m0[256*4];
__device__ float g_v0[256*4];
__device__ float g_C[4*32*36];
__device__ float g_u[16*4*32];
__device__ float g_par[256*128*36];

__host__ __device__ inline void tf2x32(uint32_t k0,uint32_t k1,uint32_t c0,uint32_t c1,
                                       uint32_t &o0,uint32_t &o1){
  uint32_t ks[3]={k0,k1,k0^k1^0x1BD11BDAu};
  uint32_t x0=c0+ks[0], x1=c1+ks[1];
  const int rA[4]={13,15,26,6}, rB[4]={17,29,16,24};
  for(int i=0;i<5;i++){
    const int* rr=(i&1)?rB:rA;
    for(int j=0;j<4;j++){ x0+=x1; int d=rr[j]; x1=(x1<<d)|(x1>>(32-d)); x1^=x0; }
    x0+=ks[(i+1)%3]; x1+=ks[(i+2)%3]+(uint32_t)(i+1);
  }
  o0=x0; o1=x1;
}

__device__ inline float erfinv_f(float x){
  float w=-log1pf(-x*x), p;
  if(w<5.0f){
    w-=2.5f;
    p=2.81022636e-08f;           p=fmaf(p,w,3.43273939e-07f);
    p=fmaf(p,w,-3.5233877e-06f); p=fmaf(p,w,-4.39150654e-06f);
    p=fmaf(p,w,0.00021858087f);  p=fmaf(p,w,-0.00125372503f);
    p=fmaf(p,w,-0.00417768164f); p=fmaf(p,w,0.246640727f);
    p=fmaf(p,w,1.50140941f);
  }else{
    w=sqrtf(w)-3.0f;
    p=-0.000200214257f;          p=fmaf(p,w,0.000100950558f);
    p=fmaf(p,w,0.00134934322f);  p=fmaf(p,w,-0.00367342844f);
    p=fmaf(p,w,0.00573950773f);  p=fmaf(p,w,-0.0076224613f);
    p=fmaf(p,w,0.00943887047f);  p=fmaf(p,w,1.00167406f);
    p=fmaf(p,w,2.83297682f);
  }
  return p*x;
}

__device__ inline float b2n(uint32_t bits){
  float f=__uint_as_float((bits>>9)|0x3f800000u)-1.0f;
  const float lo=-0.99999994f;
  float u=fmaxf(lo, f*2.0f+lo);
  return 1.41421356237f*erfinv_f(u);
}

__global__ void k_prng_all(uint32_t K0a,uint32_t K0b,uint32_t KUa,uint32_t KUb,
                           uint32_t KQa,uint32_t KQb){
  int j=blockIdx.x*blockDim.x+threadIdx.x;
  if(j<4) g_acc[j]=0.0;
  if(j>=2164736) return;
  uint32_t ka,kb; float* out; int lj;
  if(j<65536){ ka=K0a; kb=K0b; out=g_eps0; lj=j; }
  else if(j<67584){ ka=KUa; kb=KUb; out=g_epsU; lj=j-65536; }
  else { ka=KQa; kb=KQb; out=g_epsq; lj=j-67584; }
  uint32_t a,b; tf2x32(ka,kb,0u,(uint32_t)lj,a,b);
  out[lj]=b2n(a^b);
}

__global__ void k_prep(const float* Z,const float* lls,const float* los,
                       const float* m_u,const float* Lu){
  __shared__ float A[4][1056], Cs[4][1056];
  int d=threadIdx.x>>5, l=threadIdx.x&31;
  unsigned FM=0xffffffffu;
  float il[4], zl[4];
  for(int k=0;k<4;k++){ il[k]=expf(-lls[d*4+k]); zl[k]=Z[(d*32+l)*4+k]; }
  float osd=expf(los[d]);
  for(int i=0;i<32;i++){
    float s=0;
    for(int k=0;k<4;k++){ float df=(Z[(d*32+i)*4+k]-zl[k])*il[k]; s+=df*df; }
    A[d][i*33+l]=osd*expf(-0.5f*s)+((i==l)?1e-5f:0.f);
  }
  __syncwarp();
  for(int j=0;j<32;j++){
    float s=0.f;
    if(l>=j){ s=A[d][l*33+j]; for(int k=0;k<j;k++) s-=A[d][l*33+k]*A[d][j*33+k]; }
    float dj=sqrtf(__shfl_sync(FM,s,j));
    if(l==j) A[d][l*33+j]=dj; else if(l>j) A[d][l*33+j]=s/dj;
    __syncwarp();
  }
  for(int i=0;i<32;i++){
    float s=(i==l)?1.f:0.f;
    for(int k=l;k<i;k++) s-=A[d][i*33+k]*Cs[d][k*33+l];
    Cs[d][i*33+l]=(i>=l)?s/A[d][i*33+i]:0.f;
    __syncwarp();
  }
  for(int idx=l; idx<32*36; idx+=32){
    int m=idx/36, j=idx%36;
    g_C[d*1152+idx]=(j<32&&j<=m)?Cs[d][m*33+j]:0.f;
  }
  float accA=0.f;
  for(int i=0;i<32;i++){
    float a=0.f;
    for(int j=l;j<=i;j++) a+=Cs[d][i*33+j]*Lu[(d*32+j)*32+l];
    accA+=a*a;
  }
  float bq;
  { float s=0.f; for(int j=0;j<=l;j++) s+=Cs[d][l*33+j]*m_u[d*32+j]; bq=s*s; }
  float ldK=2.f*logf(A[d][l*33+l]);
  float ldS=2.f*logf(fabsf(Lu[(d*32+l)*32+l])+1e-12f);
  float tot=accA+bq-1.f+ldK-ldS;
  for(int o=16;o;o>>=1) tot+=__shfl_sync(FM,tot,l^o)*0.f+tot*0.f+__shfl_xor_sync(FM,tot,o);
  if(l==0) atomicAdd(&g_acc[1],0.5*(double)tot/(128.0*256.0));
}

__device__ inline float sigf(float x){ return 1.f/(1.f+expf(-x)); }

// ---- merged MLP (blocks 0-255) + LSTM (256-511) + uprep (512-519) ----
__global__ void __launch_bounds__(256) k_net(const float* obs,
  const float* W1,const float* b1,const float* W2,const float* b2,
  const float* W3,const float* b3,const float* W4,const float* b4,
  const float* Wih,const float* Whh,const float* bl,const float* Wm,
  const float* bm,const float* Wv,const float* bv,
  const float* m_u,const float* Lu){
  extern __shared__ __align__(16) float sm[];
  int tid=threadIdx.x, bix=blockIdx.x;
  if(bix<256){
    // ================= MLP =================
    float* W2s=sm;                    // 128*260
    float* W3s=W2s+128*260;           // 64*132
    float* W4s=W3s+64*132;            // 36*68
    float* W1s=W4s+36*68;             // 256*3
    float* b1s=W1s+768; float* b2s=b1s+256; float* b3s=b2s+128; float* b4s=b3s+64;
    float* h1t=b4s+36;                // 32*260 (h3 alias stride 68)
    float* h2t=h1t+32*260;            // 32*132
    for(int i=tid;i<128*256;i+=256) W2s[(i>>8)*260+(i&255)]=W2[i];
    for(int i=tid;i<64*128;i+=256)  W3s[(i>>7)*132+(i&127)]=W3[i];
    for(int i=tid;i<36*64;i+=256)   W4s[(i>>6)*68+(i&63)]=W4[i];
    { W1s[tid*3]=W1[tid*3]; W1s[tid*3+1]=W1[tid*3+1]; W1s[tid*3+2]=W1[tid*3+2]; b1s[tid]=b1[tid]; }
    if(tid<128) b2s[tid]=b2[tid];
    if(tid<64)  b3s[tid]=b3[tid];
    if(tid<36)  b4s[tid]=b4[tid];
    __syncthreads();
    int rb=bix*128;
    for(int tile=0;tile<4;tile++){
      int r0=rb+tile*32;
      for(int i=tid;i<32*256;i+=256){
        int r=i>>8, j=i&255, row=r0+r;
        float a=b1s[j]+W1s[j*3]*obs[row*3]+W1s[j*3+1]*obs[row*3+1]+W1s[j*3+2]*obs[row*3+2];
        h1t[r*260+j]=fmaxf(a,0.f);
      }
      __syncthreads();
      for(int i=tid;i<32*128;i+=256){
        int r=i>>7, j=i&127;
        float a=b2s[j];
        const float4* w=(const float4*)(W2s+j*260);
        const float4* hv=(const float4*)(h1t+r*260);
        #pragma unroll 8
        for(int k=0;k<64;k++){ float4 wv=w[k],h4=hv[k];
          a=fmaf(wv.x,h4.x,a); a=fmaf(wv.y,h4.y,a); a=fmaf(wv.z,h4.z,a); a=fmaf(wv.w,h4.w,a); }
        h2t[r*132+j]=fmaxf(a,0.f);
      }
      __syncthreads();
      for(int i=tid;i<32*64;i+=256){
        int r=i>>6, j=i&63;
        float a=b3s[j];
        const float4* w=(const float4*)(W3s+j*132);
        const float4* hv=(const float4*)(h2t+r*132);
        #pragma unroll 8
        for(int k=0;k<32;k++){ float4 wv=w[k],h4=hv[k];
          a=fmaf(wv.x,h4.x,a); a=fmaf(wv.y,h4.y,a); a=fmaf(wv.z,h4.z,a); a=fmaf(wv.w,h4.w,a); }
        h1t[r*68+j]=fmaxf(a,0.f);
      }
      __syncthreads();
      for(int i=tid;i<32*36;i+=256){
        int r=i/36, j=i%36;
        float a=b4s[j];
        const float4* w=(const float4*)(W4s+j*68);
        const float4* hv=(const float4*)(h1t+r*68);
        #pragma unroll
        for(int k=0;k<16;k++){ float4 wv=w[k],h4=hv[k];
          a=fmaf(wv.x,h4.x,a); a=fmaf(wv.y,h4.y,a); a=fmaf(wv.z,h4.z,a); a=fmaf(wv.w,h4.w,a); }
        g_par[(r0+r)*36+j]=a;
      }
      __syncthreads();
    }
  } else if(bix<512){
    // ================= LSTM: one batch, thread = gate row =================
    float* whh=sm;             // 256*68
    float* wih=whh+17408;      // 256*4
    float* bb =wih+1024;       // 256
    float* ob =bb+256;         // 128*4
    float* hsm=ob+512;         // 68
    float* gsm=hsm+68;         // 256
    int b=bix-256;
    for(int k=tid;k<16384;k+=256) whh[(k>>6)*68+(k&63)]=Whh[k];
    { wih[tid*4]=Wih[tid*3]; wih[tid*4+1]=Wih[tid*3+1]; wih[tid*4+2]=Wih[tid*3+2]; bb[tid]=bl[tid]; }
    for(int idx=tid;idx<384;idx+=256){ int t=idx/3,cc=idx%3; ob[t*4+cc]=obs[(b*128+t)*3+cc]; }
    if(tid<68) hsm[tid]=0.f;
    __syncthreads();
    float c=0.f;
    float w0=wih[tid*4],w1=wih[tid*4+1],w2=wih[tid*4+2],bt=bb[tid];
    const float4* wr=(const float4*)(whh+tid*68);
    for(int t=0;t<128;t++){
      float g=bt+w0*ob[t*4]+w1*ob[t*4+1]+w2*ob[t*4+2];
      #pragma unroll 4
      for(int k=0;k<16;k++){
        float4 wv=wr[k], h4=*(const float4*)(hsm+k*4);
        g=fmaf(wv.x,h4.x,g); g=fmaf(wv.y,h4.y,g); g=fmaf(wv.z,h4.z,g); g=fmaf(wv.w,h4.w,g);
      }
      gsm[tid]=g;
      __syncthreads();
      if(tid<64){
        float gi=gsm[tid],gf=gsm[64+tid],gg=gsm[128+tid],go=gsm[192+tid];
        c=sigf(gf)*c+sigf(gi)*tanhf(gg);
        hsm[tid]=sigf(go)*tanhf(c);
      }
      __syncthreads();
    }
    if(tid<4){
      int s=tid;
      float m=bm[s], pv=bv[s];
      for(int k=0;k<64;k++){ m=fmaf(Wm[s*64+k],hsm[k],m); pv=fmaf(Wv[s*64+k],hsm[k],pv); }
      float v=fmaxf(pv,0.f)+log1pf(expf(-fabsf(pv)))+1e-6f;
      g_m0[b*4+s]=m; g_v0[b*4+s]=v;
      atomicAdd(&g_acc[0],0.5*(double)(v+m*m-1.f-logf(v)));
    }
  } else {
    // ================= uprep: U = m_u + tril(Lu) epsU ; u' = C U =================
    int gt=(bix-512)*256+tid;
    int w=gt>>5, l=gt&31;
    if(w<64){
      int n=w>>2, d=w&3;
      unsigned FM=0xffffffffu;
      float e=g_epsU[(n*4+d)*32+l];
      float U=m_u[d*32+l];
      for(int k=0;k<32;k++){
        float ek=__shfl_sync(FM,e,k);
        float lv=(k<=l)?Lu[(d*32+l)*32+k]:0.f;
        U=fmaf(lv,ek,U);
      }
      float s=0.f;
      for(int j=0;j<32;j++){
        float Uj=__shfl_sync(FM,U,j);
        s=fmaf(g_C[d*1152+l*36+j],Uj,s);
      }
      g_u[(n*4+d)*32+l]=s;
    }
  }
}

// ---- main scan: warp per (n,b) chain, 128 steps ----
__global__ void __launch_bounds__(256) k_step(const float* Z,const float* lls,
    const float* los,const float* npc,const float* nem,const float* obs){
  __shared__ __align__(16) float Cs[4608];
  __shared__ __align__(16) float kb[8][132];
  int tid=threadIdx.x, wid=tid>>5, l=tid&31;
  unsigned FM=0xffffffffu;
  for(int i=tid;i<4608;i+=256) Cs[i]=g_C[i];
  int c=blockIdx.x*8+wid;
  int n=c>>8, b=c&255;
  float zl[4][4], il[4][4], osd[4], ul[4], np_[4], ine[3];
  #pragma unroll
  for(int d=0;d<4;d++){
    osd[d]=expf(los[d]); np_[d]=npc[d];
    ul[d]=g_u[(n*4+d)*32+l];
    #pragma unroll
    for(int k=0;k<4;k++){ il[d][k]=expf(-lls[d*4+k]); zl[d][k]=Z[(d*32+l)*4+k]; }
  }
  float cterm=0.f;
  #pragma unroll
  for(int o=0;o<3;o++){ ine[o]=1.f/nem[o]; cterm+=LOG2PI_F+logf(nem[o]); }
  float x[4][4];
  #pragma unroll
  for(int d=0;d<4;d++)
    #pragma unroll
    for(int k=0;k<4;k++)
      x[d][k]=g_m0[b*4+k]+sqrtf(g_v0[b*4+k])*g_eps0[((n*4+d)*256+b)*4+k];
  __syncthreads();
  double klacc=0.0, likacc=0.0;
  for(int t=0;t<128;t++){
    float kx[4];
    #pragma unroll
    for(int d=0;d<4;d++){
      float s=0.f;
      #pragma unroll
      for(int k=0;k<4;k++){ float df=(x[d][k]-zl[d][k])*il[d][k]; s=fmaf(df,df,s); }
      kx[d]=osd[d]*__expf(-0.5f*s);
    }
    __syncwarp();
    #pragma unroll
    for(int d=0;d<4;d++) kb[wid][d*32+l]=kx[d];
    __syncwarp();
    float pm[4], pv[4];
    #pragma unroll
    for(int d=0;d<4;d++){
      float w=0.f;
      const float4* Crow=(const float4*)(Cs+d*1152+l*36);
      const float4* kq=(const float4*)(kb[wid]+d*32);
      #pragma unroll
      for(int j=0;j<8;j++){
        if(j*4<=l){
          float4 cv=Crow[j], kv=kq[j];
          w=fmaf(cv.x,kv.x,w); w=fmaf(cv.y,kv.y,w);
          w=fmaf(cv.z,kv.z,w); w=fmaf(cv.w,kv.w,w);
        }
      }
      pm[d]=w*ul[d]; pv[d]=w*w;
    }
    #pragma unroll
    for(int o=16;o;o>>=1){
      #pragma unroll
      for(int d=0;d<4;d++){
        pm[d]+=__shfl_xor_sync(FM,pm[d],o);
        pv[d]+=__shfl_xor_sync(FM,pv[d],o);
      }
    }
    float gm[4], gv[4];
    #pragma unroll
    for(int d=0;d<4;d++){ gm[d]=pm[d]; gv[d]=fmaxf(osd[d]-pv[d],1e-8f); }
    const float* pr=g_par+(b*128+t)*36;
    float Atm[16], btv[4], Sl[16];
    #pragma unroll
    for(int i=0;i<16;i++) Atm[i]=pr[i];
    #pragma unroll
    for(int i=0;i<4;i++) btv[i]=pr[16+i];
    #pragma unroll
    for(int i=0;i<16;i++) Sl[i]=((i&3)<=(i>>2))?pr[20+i]:0.f;
    float qm[4];
    #pragma unroll
    for(int i=0;i<4;i++){
      float s=btv[i];
      #pragma unroll
      for(int j=0;j<4;j++) s=fmaf(Atm[i*4+j],gm[j],s);
      qm[i]=s;
    }
    float qc[16];
    #pragma unroll
    for(int i=0;i<4;i++)
      #pragma unroll
      for(int k2=0;k2<4;k2++){
        if(k2>i) continue;
        float s=0.f;
        #pragma unroll
        for(int j=0;j<4;j++) s=fmaf(Sl[i*4+j],Sl[k2*4+j],s);
        #pragma unroll
        for(int j=0;j<4;j++) s=fmaf(Atm[i*4+j]*gv[j],Atm[k2*4+j],s);
        qc[i*4+k2]=s; qc[k2*4+i]=s;
      }
    float t0=qc[0]+1e-6f, i0=rsqrtf(t0), l00=t0*i0;
    float l10=qc[4]*i0, l20=qc[8]*i0, l30=qc[12]*i0;
    float t1=qc[5]+1e-6f-l10*l10, i1=rsqrtf(t1), l11=t1*i1;
    float l21=(qc[9]-l20*l10)*i1, l31=(qc[13]-l30*l10)*i1;
    float t2=qc[10]+1e-6f-l20*l20-l21*l21, i2=rsqrtf(t2), l22=t2*i2;
    float l32=(qc[14]-l30*l20-l31*l21)*i2;
    float t3=qc[15]+1e-6f-l30*l30-l31*l31-l32*l32, i3=rsqrtf(t3), l33=t3*i3;
    float kl=0.f, prodd0=1.f;
    #pragma unroll
    for(int i=0;i<4;i++){
      float d0=gv[i]+np_[i];
      float df=gm[i]-qm[i];
      kl+=__fdividef(qc[i*4+i]+df*df,d0);
      prodd0*=d0;
    }
    float pl=l00*l11*l22*l33;
    kl=0.5f*(kl-4.f+__logf(__fdividef(prodd0,pl*pl)));
    float el=cterm;
    #pragma unroll
    for(int o=0;o<3;o++){
      float y=obs[(b*128+t)*3+o];
      float r=y-qm[o];
      el=fmaf(r*r+qc[o*4+o],ine[o],el);
    }
    el=-0.5f*el;
    klacc+=(double)kl; likacc+=(double)el;
    const float* ep=g_epsq+((t*16+n)*256+b)*4;
    float e0=ep[0],e1=ep[1],e2=ep[2],e3=ep[3];
    float xn0=qm[0]+l00*e0;
    float xn1=qm[1]+l10*e0+l11*e1;
    float xn2=qm[2]+l20*e0+l21*e1+l22*e2;
    float xn3=qm[3]+l30*e0+l31*e1+l32*e2+l33*e3;
    #pragma unroll
    for(int d=0;d<4;d++){ x[d][0]=xn0; x[d][1]=xn1; x[d][2]=xn2; x[d][3]=xn3; }
  }
  if(l==0){
    atomicAdd(&g_acc[2],klacc);
    atomicAdd(&g_acc[3],likacc);
  }
}

__global__ void k_fin(float* out){
  double qm0=g_acc[0]/256.0, gpKL=g_acc[1];
  double KL=g_acc[2]/4096.0, lik=g_acc[3]/4096.0;
  double E=-qm0-gpKL+lik-KL;
  if(lik>KL) E=-qm0-gpKL+lik/128.0-KL;
  out[0]=(float)E;
}

extern "C" void kernel_launch(void* const* d_in, const int* in_sizes, int n_in,
                              void* d_out, int out_size){
  const float* obs=(const float*)d_in[0];
  const float* Z  =(const float*)d_in[1];
  const float* lls=(const float*)d_in[2];
  const float* los=(const float*)d_in[3];
  const float* m_u=(const float*)d_in[4];
  const float* Lu =(const float*)d_in[5];
  const float* npc=(const float*)d_in[6];
  const float* nem=(const float*)d_in[7];
  const float* Wih=(const float*)d_in[8];
  const float* Whh=(const float*)d_in[9];
  const float* bl =(const float*)d_in[10];
  const float* Wm =(const float*)d_in[11];
  const float* bm =(const float*)d_in[12];
  const float* Wv =(const float*)d_in[13];
  const float* bv =(const float*)d_in[14];
  const float* W1 =(const float*)d_in[15];
  const float* b1 =(const float*)d_in[16];
  const float* W2 =(const float*)d_in[17];
  const float* b2 =(const float*)d_in[18];
  const float* W3 =(const float*)d_in[19];
  const float* b3 =(const float*)d_in[20];
  const float* W4 =(const float*)d_in[21];
  const float* b4 =(const float*)d_in[22];

  uint32_t K0a,K0b,KUa,KUb,KQa,KQb;
  tf2x32(0u,42u,0u,0u,K0a,K0b);
  tf2x32(0u,42u,0u,1u,KUa,KUb);
  tf2x32(0u,42u,0u,2u,KQa,KQb);

  cudaFuncSetAttribute(k_net, cudaFuncAttributeMaxDynamicSharedMemorySize, 231888);

  k_prng_all<<<8457,256>>>(K0a,K0b,KUa,KUb,KQa,KQb);       // 0
  k_prep<<<1,128>>>(Z,lls,los,m_u,Lu);                     // 1
  k_net<<<520,256,231888>>>(obs,W1,b1,W2,b2,W3,b3,W4,b4,   // 2
                            Wih,Whh,bl,Wm,bm,Wv,bv,m_u,Lu);
  k_step<<<512,256>>>(Z,lls,los,npc,nem,obs);              // 3  (ncu -s 5 lands here)
  k_fin<<<1,1>>>((float*)d_out);                           // 4
}

// round 17
// speedup vs baseline: 1.6319x; 1.1519x over previous
#include <cuda_runtime.h>
#include <cstdint>

#define LOG2PI_F 1.8378770664093453f

__device__ double g_acc[4];
__device__ float g_eps0[16*4*256*4];
__device__ float g_epsU[16*4*32];
__device__ float g_epsq[128*16*256*4];
__device__ float g_m0[256*4];
__device__ float g_v0[256*4];
__device__ float g_C[4*32*36];
__device__ float g_u[16*4*32];
__device__ float g_par[256*128*36];

__host__ __device__ inline void tf2x32(uint32_t k0,uint32_t k1,uint32_t c0,uint32_t c1,
                                       uint32_t &o0,uint32_t &o1){
  uint32_t ks[3]={k0,k1,k0^k1^0x1BD11BDAu};
  uint32_t x0=c0+ks[0], x1=c1+ks[1];
  const int rA[4]={13,15,26,6}, rB[4]={17,29,16,24};
  for(int i=0;i<5;i++){
    const int* rr=(i&1)?rB:rA;
    for(int j=0;j<4;j++){ x0+=x1; int dd=rr[j]; x1=(x1<<dd)|(x1>>(32-dd)); x1^=x0; }
    x0+=ks[(i+1)%3]; x1+=ks[(i+2)%3]+(uint32_t)(i+1);
  }
  o0=x0; o1=x1;
}

__device__ inline float erfinv_f(float x){
  float w=-log1pf(-x*x), p;
  if(w<5.0f){
    w-=2.5f;
    p=2.81022636e-08f;           p=fmaf(p,w,3.43273939e-07f);
    p=fmaf(p,w,-3.5233877e-06f); p=fmaf(p,w,-4.39150654e-06f);
    p=fmaf(p,w,0.00021858087f);  p=fmaf(p,w,-0.00125372503f);
    p=fmaf(p,w,-0.00417768164f); p=fmaf(p,w,0.246640727f);
    p=fmaf(p,w,1.50140941f);
  }else{
    w=sqrtf(w)-3.0f;
    p=-0.000200214257f;          p=fmaf(p,w,0.000100950558f);
    p=fmaf(p,w,0.00134934322f);  p=fmaf(p,w,-0.00367342844f);
    p=fmaf(p,w,0.00573950773f);  p=fmaf(p,w,-0.0076224613f);
    p=fmaf(p,w,0.00943887047f);  p=fmaf(p,w,1.00167406f);
    p=fmaf(p,w,2.83297682f);
  }
  return p*x;
}

__device__ inline float b2n(uint32_t bits){
  float f=__uint_as_float((bits>>9)|0x3f800000u)-1.0f;
  const float lo=-0.99999994f;
  float u=fmaxf(lo, f*2.0f+lo);
  return 1.41421356237f*erfinv_f(u);
}

__global__ void k_prng_all(uint32_t K0a,uint32_t K0b,uint32_t KUa,uint32_t KUb,
                           uint32_t KQa,uint32_t KQb){
  int j=blockIdx.x*blockDim.x+threadIdx.x;
  if(j<4) g_acc[j]=0.0;
  if(j>=2164736) return;
  uint32_t ka,kb; float* out; int lj;
  if(j<65536){ ka=K0a; kb=K0b; out=g_eps0; lj=j; }
  else if(j<67584){ ka=KUa; kb=KUb; out=g_epsU; lj=j-65536; }
  else { ka=KQa; kb=KQb; out=g_epsq; lj=j-67584; }
  uint32_t a,b; tf2x32(ka,kb,0u,(uint32_t)lj,a,b);
  out[lj]=b2n(a^b);
}

__global__ void k_prep(const float* Z,const float* lls,const float* los,
                       const float* m_u,const float* Lu){
  __shared__ float A[4][1056], Cs[4][1056];
  int d=threadIdx.x>>5, l=threadIdx.x&31;
  unsigned FM=0xffffffffu;
  float il[4], zl[4];
  for(int k=0;k<4;k++){ il[k]=expf(-lls[d*4+k]); zl[k]=Z[(d*32+l)*4+k]; }
  float osd=expf(los[d]);
  for(int i=0;i<32;i++){
    float s=0;
    for(int k=0;k<4;k++){ float df=(Z[(d*32+i)*4+k]-zl[k])*il[k]; s+=df*df; }
    A[d][i*33+l]=osd*expf(-0.5f*s)+((i==l)?1e-5f:0.f);
  }
  __syncwarp();
  for(int j=0;j<32;j++){
    float s=0.f;
    if(l>=j){ s=A[d][l*33+j]; for(int k=0;k<j;k++) s-=A[d][l*33+k]*A[d][j*33+k]; }
    float dj=sqrtf(__shfl_sync(FM,s,j));
    if(l==j) A[d][l*33+j]=dj; else if(l>j) A[d][l*33+j]=s/dj;
    __syncwarp();
  }
  for(int i=0;i<32;i++){
    float s=(i==l)?1.f:0.f;
    for(int k=l;k<i;k++) s-=A[d][i*33+k]*Cs[d][k*33+l];
    Cs[d][i*33+l]=(i>=l)?s/A[d][i*33+i]:0.f;
    __syncwarp();
  }
  for(int idx=l; idx<32*36; idx+=32){
    int m=idx/36, j=idx%36;
    g_C[d*1152+idx]=(j<32&&j<=m)?Cs[d][m*33+j]:0.f;
  }
  float accA=0.f;
  for(int i=0;i<32;i++){
    float a=0.f;
    for(int j=l;j<=i;j++) a+=Cs[d][i*33+j]*Lu[(d*32+j)*32+l];
    accA+=a*a;
  }
  float bq;
  { float s=0.f; for(int j=0;j<=l;j++) s+=Cs[d][l*33+j]*m_u[d*32+j]; bq=s*s; }
  float ldK=2.f*logf(A[d][l*33+l]);
  float ldS=2.f*logf(fabsf(Lu[(d*32+l)*32+l])+1e-12f);
  float tot=accA+bq-1.f+ldK-ldS;
  for(int o=16;o;o>>=1) tot+=__shfl_xor_sync(FM,tot,o);
  if(l==0) atomicAdd(&g_acc[1],0.5*(double)tot/(128.0*256.0));
}

__device__ inline float sigf(float x){ return 1.f/(1.f+expf(-x)); }

// ---- merged MLP (0-255, 4x4 register tiled) + LSTM (256-511) + uprep (512-519) ----
__global__ void __launch_bounds__(256) k_net(const float* obs,
  const float* W1,const float* b1,const float* W2,const float* b2,
  const float* W3,const float* b3,const float* W4,const float* b4,
  const float* Wih,const float* Whh,const float* bl,const float* Wm,
  const float* bm,const float* Wv,const float* bv,
  const float* m_u,const float* Lu){
  extern __shared__ __align__(16) float sm[];
  int tid=threadIdx.x, bix=blockIdx.x;
  if(bix<256){
    // ====== MLP: 128 rows/block, weights streamed from L2 ======
    float* W1s=sm;            // 768
    float* b1s=sm+768;        // 256
    float* b2s=sm+1024;       // 128
    float* b3s=sm+1152;       // 64
    float* b4s=sm+1216;       // 64 (36 used)
    float* obst=sm+1280;      // 128
    float* h1=sm+1408;        // 32*260  (h3 aliases, stride 68)
    float* h2=sm+9728;        // 32*132
    { W1s[tid*3]=W1[tid*3]; W1s[tid*3+1]=W1[tid*3+1]; W1s[tid*3+2]=W1[tid*3+2]; b1s[tid]=b1[tid]; }
    if(tid<128) b2s[tid]=b2[tid];
    if(tid<64)  b3s[tid]=b3[tid];
    if(tid<36)  b4s[tid]=b4[tid];
    int rg=tid>>5, cg=tid&31;
    int rb=bix*128;
    for(int tile=0;tile<4;tile++){
      int r0=rb+tile*32;
      if(tid<96){ int r=tid/3, cc=tid-3*(tid/3); obst[r*4+cc]=obs[(r0+r)*3+cc]; }
      __syncthreads();
      for(int i=tid;i<32*256;i+=256){
        int r=i>>8, j=i&255;
        float a=b1s[j]+W1s[j*3]*obst[r*4]+W1s[j*3+1]*obst[r*4+1]+W1s[j*3+2]*obst[r*4+2];
        h1[r*260+j]=fmaxf(a,0.f);
      }
      __syncthreads();
      { // L2: 32x128, k=256, 4x4 tile
        float acc[4][4]={};
        for(int k=0;k<256;k+=4){
          float4 h40=*(const float4*)(h1+(rg*4+0)*260+k);
          float4 h41=*(const float4*)(h1+(rg*4+1)*260+k);
          float4 h42=*(const float4*)(h1+(rg*4+2)*260+k);
          float4 h43=*(const float4*)(h1+(rg*4+3)*260+k);
          #pragma unroll
          for(int m=0;m<4;m++){
            float4 w=__ldg((const float4*)(W2+(cg*4+m)*256+k));
            acc[0][m]=fmaf(h40.x,w.x,fmaf(h40.y,w.y,fmaf(h40.z,w.z,fmaf(h40.w,w.w,acc[0][m]))));
            acc[1][m]=fmaf(h41.x,w.x,fmaf(h41.y,w.y,fmaf(h41.z,w.z,fmaf(h41.w,w.w,acc[1][m]))));
            acc[2][m]=fmaf(h42.x,w.x,fmaf(h42.y,w.y,fmaf(h42.z,w.z,fmaf(h42.w,w.w,acc[2][m]))));
            acc[3][m]=fmaf(h43.x,w.x,fmaf(h43.y,w.y,fmaf(h43.z,w.z,fmaf(h43.w,w.w,acc[3][m]))));
          }
        }
        #pragma unroll
        for(int i2=0;i2<4;i2++){
          float4 o;
          o.x=fmaxf(acc[i2][0]+b2s[cg*4  ],0.f);
          o.y=fmaxf(acc[i2][1]+b2s[cg*4+1],0.f);
          o.z=fmaxf(acc[i2][2]+b2s[cg*4+2],0.f);
          o.w=fmaxf(acc[i2][3]+b2s[cg*4+3],0.f);
          *(float4*)(h2+(rg*4+i2)*132+cg*4)=o;
        }
      }
      __syncthreads();
      { // L3: 32x64, k=128, 4x2 tile -> h3 (aliases h1, stride 68)
        float acc[4][2]={};
        for(int k=0;k<128;k+=4){
          float4 h40=*(const float4*)(h2+(rg*4+0)*132+k);
          float4 h41=*(const float4*)(h2+(rg*4+1)*132+k);
          float4 h42=*(const float4*)(h2+(rg*4+2)*132+k);
          float4 h43=*(const float4*)(h2+(rg*4+3)*132+k);
          #pragma unroll
          for(int m=0;m<2;m++){
            float4 w=__ldg((const float4*)(W3+(cg*2+m)*128+k));
            acc[0][m]=fmaf(h40.x,w.x,fmaf(h40.y,w.y,fmaf(h40.z,w.z,fmaf(h40.w,w.w,acc[0][m]))));
            acc[1][m]=fmaf(h41.x,w.x,fmaf(h41.y,w.y,fmaf(h41.z,w.z,fmaf(h41.w,w.w,acc[1][m]))));
            acc[2][m]=fmaf(h42.x,w.x,fmaf(h42.y,w.y,fmaf(h42.z,w.z,fmaf(h42.w,w.w,acc[2][m]))));
            acc[3][m]=fmaf(h43.x,w.x,fmaf(h43.y,w.y,fmaf(h43.z,w.z,fmaf(h43.w,w.w,acc[3][m]))));
          }
        }
        #pragma unroll
        for(int i2=0;i2<4;i2++){
          h1[(rg*4+i2)*68+cg*2  ]=fmaxf(acc[i2][0]+b3s[cg*2  ],0.f);
          h1[(rg*4+i2)*68+cg*2+1]=fmaxf(acc[i2][1]+b3s[cg*2+1],0.f);
        }
      }
      __syncthreads();
      for(int i=tid;i<1152;i+=256){
        int r=i/36, j=i-36*(i/36);
        float a=b4s[j];
        for(int k=0;k<64;k+=4){
          float4 h4=*(const float4*)(h1+r*68+k);
          float4 w=__ldg((const float4*)(W4+j*64+k));
          a=fmaf(h4.x,w.x,fmaf(h4.y,w.y,fmaf(h4.z,w.z,fmaf(h4.w,w.w,a))));
        }
        g_par[(r0+r)*36+j]=a;
      }
      __syncthreads();
    }
  } else if(bix<512){
    // ====== LSTM: one batch, thread = gate row ======
    float* whh=sm;             // 256*68
    float* wih=whh+17408;      // 256*4
    float* bb =wih+1024;       // 256
    float* ob =bb+256;         // 128*4
    float* hsm=ob+512;         // 68
    float* gsm=hsm+68;         // 256
    int b=bix-256;
    for(int k=tid;k<16384;k+=256) whh[(k>>6)*68+(k&63)]=Whh[k];
    { wih[tid*4]=Wih[tid*3]; wih[tid*4+1]=Wih[tid*3+1]; wih[tid*4+2]=Wih[tid*3+2]; bb[tid]=bl[tid]; }
    for(int idx=tid;idx<384;idx+=256){ int t=idx/3,cc=idx%3; ob[t*4+cc]=obs[(b*128+t)*3+cc]; }
    if(tid<68) hsm[tid]=0.f;
    __syncthreads();
    float c=0.f;
    float w0=wih[tid*4],w1=wih[tid*4+1],w2=wih[tid*4+2],bt=bb[tid];
    const float4* wr=(const float4*)(whh+tid*68);
    for(int t=0;t<128;t++){
      float g=bt+w0*ob[t*4]+w1*ob[t*4+1]+w2*ob[t*4+2];
      #pragma unroll 4
      for(int k=0;k<16;k++){
        float4 wv=wr[k], h4=*(const float4*)(hsm+k*4);
        g=fmaf(wv.x,h4.x,g); g=fmaf(wv.y,h4.y,g); g=fmaf(wv.z,h4.z,g); g=fmaf(wv.w,h4.w,g);
      }
      gsm[tid]=g;
      __syncthreads();
      if(tid<64){
        float gi=gsm[tid],gf=gsm[64+tid],gg=gsm[128+tid],go=gsm[192+tid];
        c=sigf(gf)*c+sigf(gi)*tanhf(gg);
        hsm[tid]=sigf(go)*tanhf(c);
      }
      __syncthreads();
    }
    if(tid<4){
      int s=tid;
      float m=bm[s], pv=bv[s];
      for(int k=0;k<64;k++){ m=fmaf(Wm[s*64+k],hsm[k],m); pv=fmaf(Wv[s*64+k],hsm[k],pv); }
      float v=fmaxf(pv,0.f)+log1pf(expf(-fabsf(pv)))+1e-6f;
      g_m0[b*4+s]=m; g_v0[b*4+s]=v;
      atomicAdd(&g_acc[0],0.5*(double)(v+m*m-1.f-logf(v)));
    }
  } else {
    // ====== uprep ======
    int gt=(bix-512)*256+tid;
    int w=gt>>5, l=gt&31;
    if(w<64){
      int n=w>>2, d=w&3;
      unsigned FM=0xffffffffu;
      float e=g_epsU[(n*4+d)*32+l];
      float U=m_u[d*32+l];
      for(int k=0;k<32;k++){
        float ek=__shfl_sync(FM,e,k);
        float lv=(k<=l)?Lu[(d*32+l)*32+k]:0.f;
        U=fmaf(lv,ek,U);
      }
      float s=0.f;
      for(int j=0;j<32;j++){
        float Uj=__shfl_sync(FM,U,j);
        s=fmaf(g_C[d*1152+l*36+j],Uj,s);
      }
      g_u[(n*4+d)*32+l]=s;
    }
  }
}

// ---- main scan: warp per (n,b) chain, 8 lanes per GP dim ----
__global__ void __launch_bounds__(256,3) k_step(const float* Z,const float* lls,
    const float* los,const float* npc,const float* nem,const float* obs){
  __shared__ __align__(16) float Csp[4752];   // 4 dims, stride 1188 (rows of 36)
  __shared__ __align__(16) float Zs[512];
  __shared__ __align__(16) float kb[8*144];   // per warp: 4 dims * 36
  int tid=threadIdx.x, wid=tid>>5, l=tid&31;
  unsigned FM=0xffffffffu;
  for(int i=tid;i<4752;i+=256){ int dd=i/1188, rem=i-dd*1188; Csp[i]=(rem<1152)?g_C[dd*1152+rem]:0.f; }
  for(int i=tid;i<512;i+=256) Zs[i]=Z[i];
  int c=blockIdx.x*8+wid;
  int n=c>>8, b=c&255;
  int d=l>>3, s=l&7;
  float il[4], ul[4], np_[4], ine[3];
  #pragma unroll
  for(int k=0;k<4;k++) il[k]=expf(-lls[d*4+k]);
  float osd=expf(los[d]);
  #pragma unroll
  for(int i=0;i<4;i++) ul[i]=g_u[(n*4+d)*32+s+8*i];
  #pragma unroll
  for(int i=0;i<4;i++) np_[i]=npc[i];
  float cterm=0.f;
  #pragma unroll
  for(int o=0;o<3;o++){ ine[o]=1.f/nem[o]; cterm+=LOG2PI_F+logf(nem[o]); }
  float x[4];
  #pragma unroll
  for(int k=0;k<4;k++)
    x[k]=g_m0[b*4+k]+sqrtf(g_v0[b*4+k])*g_eps0[((n*4+d)*256+b)*4+k];
  __syncthreads();
  float* kbw=kb+wid*144+d*36;
  const float4* kq=(const float4*)kbw;
  double klacc=0.0, likacc=0.0;
  for(int t=0;t<128;t++){
    // kxz: 4 rows of own dim
    float kx[4];
    #pragma unroll
    for(int i=0;i<4;i++){
      float4 zq=*(const float4*)(Zs+(d*32+s+8*i)*4);
      float d0=(x[0]-zq.x)*il[0], d1=(x[1]-zq.y)*il[1];
      float d2=(x[2]-zq.z)*il[2], d3=(x[3]-zq.w)*il[3];
      float ss=fmaf(d0,d0,fmaf(d1,d1,fmaf(d2,d2,d3*d3)));
      kx[i]=osd*__expf(-0.5f*ss);
    }
    __syncwarp();
    kbw[s]=kx[0]; kbw[s+8]=kx[1]; kbw[s+16]=kx[2]; kbw[s+24]=kx[3];
    __syncwarp();
    // triangular matvec w = C kx (C zero-padded -> uniform trips)
    float w[4];
    #pragma unroll
    for(int i=0;i<4;i++){
      const float4* Cr=(const float4*)(Csp+d*1188+(s+8*i)*36);
      float acc=0.f;
      #pragma unroll
      for(int jb=0;jb<2*i+2;jb++){
        float4 cv=Cr[jb], kv=kq[jb];
        acc=fmaf(cv.x,kv.x,fmaf(cv.y,kv.y,fmaf(cv.z,kv.z,fmaf(cv.w,kv.w,acc))));
      }
      w[i]=acc;
    }
    float pm=fmaf(w[0],ul[0],fmaf(w[1],ul[1],fmaf(w[2],ul[2],w[3]*ul[3])));
    float pv=fmaf(w[0],w[0],fmaf(w[1],w[1],fmaf(w[2],w[2],w[3]*w[3])));
    #pragma unroll
    for(int o=1;o<8;o<<=1){ pm+=__shfl_xor_sync(FM,pm,o); pv+=__shfl_xor_sync(FM,pv,o); }
    float gvd=fmaxf(osd-pv,1e-8f);
    float gm[4], gv[4];
    #pragma unroll
    for(int dd=0;dd<4;dd++){
      gm[dd]=__shfl_sync(FM,pm,dd*8);
      gv[dd]=__shfl_sync(FM,gvd,dd*8);
    }
    // epilogue (uniform across warp)
    const float* pr=g_par+(b*128+t)*36;
    float Atm[16], btv[4], Sl[16];
    #pragma unroll
    for(int i=0;i<16;i++) Atm[i]=pr[i];
    #pragma unroll
    for(int i=0;i<4;i++) btv[i]=pr[16+i];
    #pragma unroll
    for(int i=0;i<16;i++) Sl[i]=((i&3)<=(i>>2))?pr[20+i]:0.f;
    float qm[4];
    #pragma unroll
    for(int i=0;i<4;i++){
      float ss=btv[i];
      #pragma unroll
      for(int j=0;j<4;j++) ss=fmaf(Atm[i*4+j],gm[j],ss);
      qm[i]=ss;
    }
    float qc[16];
    #pragma unroll
    for(int i=0;i<4;i++)
      #pragma unroll
      for(int k2=0;k2<4;k2++){
        if(k2>i) continue;
        float ss=0.f;
        #pragma unroll
        for(int j=0;j<4;j++) ss=fmaf(Sl[i*4+j],Sl[k2*4+j],ss);
        #pragma unroll
        for(int j=0;j<4;j++) ss=fmaf(Atm[i*4+j]*gv[j],Atm[k2*4+j],ss);
        qc[i*4+k2]=ss; qc[k2*4+i]=ss;
      }
    float t0=qc[0]+1e-6f, i0=rsqrtf(t0), l00=t0*i0;
    float l10=qc[4]*i0, l20=qc[8]*i0, l30=qc[12]*i0;
    float t1=qc[5]+1e-6f-l10*l10, i1=rsqrtf(t1), l11=t1*i1;
    float l21=(qc[9]-l20*l10)*i1, l31=(qc[13]-l30*l10)*i1;
    float t2=qc[10]+1e-6f-l20*l20-l21*l21, i2=rsqrtf(t2), l22=t2*i2;
    float l32=(qc[14]-l30*l20-l31*l21)*i2;
    float t3=qc[15]+1e-6f-l30*l30-l31*l31-l32*l32, i3=rsqrtf(t3), l33=t3*i3;
    float kl=0.f, prodd0=1.f;
    #pragma unroll
    for(int i=0;i<4;i++){
      float d0=gv[i]+np_[i];
      float df=gm[i]-qm[i];
      kl+=__fdividef(qc[i*4+i]+df*df,d0);
      prodd0*=d0;
    }
    float pl=l00*l11*l22*l33;
    kl=0.5f*(kl-4.f+__logf(__fdividef(prodd0,pl*pl)));
    float el=cterm;
    #pragma unroll
    for(int o=0;o<3;o++){
      float y=obs[(b*128+t)*3+o];
      float r=y-qm[o];
      el=fmaf(r*r+qc[o*4+o],ine[o],el);
    }
    el=-0.5f*el;
    klacc+=(double)kl; likacc+=(double)el;
    const float* ep=g_epsq+((t*16+n)*256+b)*4;
    float e0=ep[0],e1=ep[1],e2=ep[2],e3=ep[3];
    x[0]=qm[0]+l00*e0;
    x[1]=qm[1]+l10*e0+l11*e1;
    x[2]=qm[2]+l20*e0+l21*e1+l22*e2;
    x[3]=qm[3]+l30*e0+l31*e1+l32*e2+l33*e3;
  }
  if(l==0){
    atomicAdd(&g_acc[2],klacc);
    atomicAdd(&g_acc[3],likacc);
  }
}

__global__ void k_fin(float* out){
  double qm0=g_acc[0]/256.0, gpKL=g_acc[1];
  double KL=g_acc[2]/4096.0, lik=g_acc[3]/4096.0;
  double E=-qm0-gpKL+lik-KL;
  if(lik>KL) E=-qm0-gpKL+lik/128.0-KL;
  out[0]=(float)E;
}

extern "C" void kernel_launch(void* const* d_in, const int* in_sizes, int n_in,
                              void* d_out, int out_size){
  const float* obs=(const float*)d_in[0];
  const float* Z  =(const float*)d_in[1];
  const float* lls=(const float*)d_in[2];
  const float* los=(const float*)d_in[3];
  const float* m_u=(const float*)d_in[4];
  const float* Lu =(const float*)d_in[5];
  const float* npc=(const float*)d_in[6];
  const float* nem=(const float*)d_in[7];
  const float* Wih=(const float*)d_in[8];
  const float* Whh=(const float*)d_in[9];
  const float* bl =(const float*)d_in[10];
  const float* Wm =(const float*)d_in[11];
  const float* bm =(const float*)d_in[12];
  const float* Wv =(const float*)d_in[13];
  const float* bv =(const float*)d_in[14];
  const float* W1 =(const float*)d_in[15];
  const float* b1 =(const float*)d_in[16];
  const float* W2 =(const float*)d_in[17];
  const float* b2 =(const float*)d_in[18];
  const float* W3 =(const float*)d_in[19];
  const float* b3 =(const float*)d_in[20];
  const float* W4 =(const float*)d_in[21];
  const float* b4 =(const float*)d_in[22];

  uint32_t K0a,K0b,KUa,KUb,KQa,KQb;
  tf2x32(0u,42u,0u,0u,K0a,K0b);
  tf2x32(0u,42u,0u,1u,KUa,KUb);
  tf2x32(0u,42u,0u,2u,KQa,KQb);

  cudaFuncSetAttribute(k_net, cudaFuncAttributeMaxDynamicSharedMemorySize, 78096);

  k_prng_all<<<8457,256>>>(K0a,K0b,KUa,KUb,KQa,KQb);       // 0
  k_prep<<<1,128>>>(Z,lls,los,m_u,Lu);                     // 1
  k_net<<<520,256,78096>>>(obs,W1,b1,W2,b2,W3,b3,W4,b4,    // 2
                           Wih,Whh,bl,Wm,bm,Wv,bv,m_u,Lu);
  k_step<<<512,256>>>(Z,lls,los,npc,nem,obs);              // 3  (profiled)
  k_fin<<<1,1>>>((float*)d_out);                           // 4
}